// round 8
// baseline (speedup 1.0000x reference)
#include <cuda_runtime.h>
#include <math.h>
#include <stdint.h>

#define MAXN   500000
#define NBATCH 4096

// stride (in 32-bit words) of act / W smem rows
#define SW 136
#define WROW_WORDS (128 * SW)          // 17408 words = 69632 B per 128x128 tile
#define WTILE_V16  (WROW_WORDS / 4)    // 4352 16-byte chunks

// ---- static scratch ----
__device__ __align__(16) float    g_keys[(size_t)MAXN * 128];
__device__ __align__(16) float    g_k2  [(size_t)MAXN * 128];
__device__ __align__(16) uint32_t g_wprep[10 * WROW_WORDS];   // tf32, [n][k-perm], stride 136
__device__ int g_segstart[NBATCH + 1];

struct SmemQ {
    uint32_t act[WROW_WORDS];      // operand tile (tf32, k-permuted); reused as y (float)
    uint32_t w[2][WROW_WORDS];     // two full weight tiles
    float    ssum[128][4];
    float    ssq [128][4];
    int      sbatch[128];
};

__device__ __forceinline__ float mish_f(float x) {
    float sp = (x > 20.f) ? x : log1pf(__expf(x));
    return x * tanhf(sp);
}
__device__ __forceinline__ uint32_t f2tf(float f) {
    uint32_t u; asm("cvt.rna.tf32.f32 %0, %1;" : "=r"(u) : "f"(f)); return u;
}
__device__ __forceinline__ uint32_t smem_u32(const void* p) {
    uint32_t a;
    asm("{ .reg .u64 t; cvta.to.shared.u64 t, %1; cvt.u32.u64 %0, t; }" : "=r"(a) : "l"(p));
    return a;
}
__device__ __forceinline__ void mma8(float c[4], uint32_t a0, uint32_t a1, uint32_t a2,
                                     uint32_t a3, uint32_t b0, uint32_t b1) {
    asm volatile("mma.sync.aligned.m16n8k8.row.col.f32.tf32.tf32.f32 "
        "{%0,%1,%2,%3},{%4,%5,%6,%7},{%8,%9},{%0,%1,%2,%3};"
        : "+f"(c[0]), "+f"(c[1]), "+f"(c[2]), "+f"(c[3])
        : "r"(a0), "r"(a1), "r"(a2), "r"(a3), "r"(b0), "r"(b1));
}

// k-permutation: pairs (t, t+4) within each 8-group become adjacent
__device__ __forceinline__ int kperm(int k) {
    return (k & ~7) | ((k & 3) << 1) | ((k >> 2) & 1);
}

// ---- segment starts via binary search over sorted batch ----
__global__ void segstart_kernel(const int* __restrict__ batch, int n, int* __restrict__ segstart) {
    int b = blockIdx.x * blockDim.x + threadIdx.x;
    if (b > NBATCH) return;
    int lo = 0, hi = n;
    while (lo < hi) { int m = (lo + hi) >> 1; if (batch[m] < b) lo = m + 1; else hi = m; }
    segstart[b] = lo;
}

// ---- weight prep: W[k][n] fp32 row-major -> g_wprep[wi]: [n][k-perm] tf32, stride 136 ----
__global__ void prep_all(const float* w0, const float* w1, const float* w2, const float* w3,
                         const float* w4, const float* w5, const float* w6, const float* w7,
                         const float* w8, const float* w9) {
    const float* srcs[10] = {w0, w1, w2, w3, w4, w5, w6, w7, w8, w9};
    int wi = blockIdx.y;
    const float* W = srcs[wi];
    int e = blockIdx.x * 256 + threadIdx.x;     // 0..16383
    int k = e >> 7, nn = e & 127;
    g_wprep[wi * WROW_WORDS + nn * SW + kperm(k)] = f2tf(W[e]);
}

// ---- cp.async copy of one prepped weight tile into smem ----
__device__ __forceinline__ void fill_w_async(uint32_t dst_smem, const uint32_t* __restrict__ gsrc,
                                             int tid) {
#pragma unroll
    for (int i = 0; i < 9; i++) {
        int idx = tid + i * 512;
        if (idx < WTILE_V16)
            asm volatile("cp.async.cg.shared.global [%0], [%1], 16;"
                         :: "r"(dst_smem + idx * 16), "l"(gsrc + idx * 4) : "memory");
    }
    asm volatile("cp.async.commit_group;" ::: "memory");
}
#define CP_WAIT() asm volatile("cp.async.wait_group 0;" ::: "memory")

// ---- load 128x128 fp32 tile -> smem act (tf32, k-permuted), zero-padded. 512 threads ----
__device__ __forceinline__ void fill_act(SmemQ* s, const float* __restrict__ src,
                                         int row0, int n, int tid) {
#pragma unroll
    for (int i = 0; i < 8; i++) {
        int e = tid + i * 512;
        int r = e >> 5, k4 = (e & 31) * 4;
        int gr = row0 + r;
        float4 v = make_float4(0.f, 0.f, 0.f, 0.f);
        if (gr < n) v = *(const float4*)(src + (size_t)gr * 128 + k4);
        int b8 = r * SW + (k4 & ~7) + ((k4 & 4) ? 1 : 0);
        s->act[b8 + 0] = f2tf(v.x);
        s->act[b8 + 2] = f2tf(v.y);
        s->act[b8 + 4] = f2tf(v.z);
        s->act[b8 + 6] = f2tf(v.w);
    }
}

// ---- GEMM core: acc = act @ W (both smem-resident, k-permuted). No internal syncs. ----
// 16 warps, warp tile 32x32: rows wm*32 + {g, g+8, g+16, g+24}, cols wn*32 + j*8 + 2tig(+1)
__device__ __forceinline__ void gemm_core(const SmemQ* s, int wbuf, float acc[2][4][4],
                                          int wm, int wn, int g, int tig) {
    const uint2* A = (const uint2*)s->act;
    const uint2* B = (const uint2*)s->w[wbuf];
    const int ra = (wm * 32 + g) * (SW / 2) + tig;
    const int rb = (wn * 32 + g) * (SW / 2) + tig;
#pragma unroll
    for (int mt = 0; mt < 2; mt++)
#pragma unroll
        for (int j = 0; j < 4; j++)
#pragma unroll
            for (int c = 0; c < 4; c++) acc[mt][j][c] = 0.f;

#pragma unroll
    for (int kk = 0; kk < 16; kk++) {
        const int ko = kk * 4;
        uint2 a0 = A[ra + ko];
        uint2 a1 = A[ra + 8  * (SW / 2) + ko];
        uint2 a2 = A[ra + 16 * (SW / 2) + ko];
        uint2 a3 = A[ra + 24 * (SW / 2) + ko];
        uint2 b0 = B[rb + ko];
        uint2 b1 = B[rb + 8  * (SW / 2) + ko];
        uint2 b2 = B[rb + 16 * (SW / 2) + ko];
        uint2 b3 = B[rb + 24 * (SW / 2) + ko];
        mma8(acc[0][0], a0.x, a1.x, a0.y, a1.y, b0.x, b0.y);
        mma8(acc[0][1], a0.x, a1.x, a0.y, a1.y, b1.x, b1.y);
        mma8(acc[0][2], a0.x, a1.x, a0.y, a1.y, b2.x, b2.y);
        mma8(acc[0][3], a0.x, a1.x, a0.y, a1.y, b3.x, b3.y);
        mma8(acc[1][0], a2.x, a3.x, a2.y, a3.y, b0.x, b0.y);
        mma8(acc[1][1], a2.x, a3.x, a2.y, a3.y, b1.x, b1.y);
        mma8(acc[1][2], a2.x, a3.x, a2.y, a3.y, b2.x, b2.y);
        mma8(acc[1][3], a2.x, a3.x, a2.y, a3.y, b3.x, b3.y);
    }
}

// ---- bias + layernorm + mish on acc; write result (tf32, k-permuted) into act ----
__device__ __forceinline__ void ln_mish_act(SmemQ* s, float acc[2][4][4],
    const float* __restrict__ bias, const float* __restrict__ gam, const float* __restrict__ bet,
    int wm, int wn, int g, int tig)
{
    float2 bv[4], gv[4], bb[4];
#pragma unroll
    for (int j = 0; j < 4; j++) {
        int cc = wn * 32 + j * 8 + 2 * tig;
        bv[j] = *(const float2*)(bias + cc);
        gv[j] = *(const float2*)(gam + cc);
        bb[j] = *(const float2*)(bet + cc);
    }
#pragma unroll
    for (int mt = 0; mt < 2; mt++) {
        float s0 = 0.f, q0 = 0.f, s1 = 0.f, q1 = 0.f;
#pragma unroll
        for (int j = 0; j < 4; j++) {
            float a0 = acc[mt][j][0] + bv[j].x, a1 = acc[mt][j][1] + bv[j].y;
            float a2 = acc[mt][j][2] + bv[j].x, a3 = acc[mt][j][3] + bv[j].y;
            acc[mt][j][0] = a0; acc[mt][j][1] = a1; acc[mt][j][2] = a2; acc[mt][j][3] = a3;
            s0 += a0 + a1; q0 += a0 * a0 + a1 * a1;
            s1 += a2 + a3; q1 += a2 * a2 + a3 * a3;
        }
#pragma unroll
        for (int o = 1; o <= 2; o <<= 1) {
            s0 += __shfl_xor_sync(0xffffffffu, s0, o);
            q0 += __shfl_xor_sync(0xffffffffu, q0, o);
            s1 += __shfl_xor_sync(0xffffffffu, s1, o);
            q1 += __shfl_xor_sync(0xffffffffu, q1, o);
        }
        if (tig == 0) {
            int r = wm * 32 + mt * 16 + g;
            s->ssum[r][wn] = s0; s->ssq[r][wn] = q0;
            s->ssum[r + 8][wn] = s1; s->ssq[r + 8][wn] = q1;
        }
    }
    __syncthreads();   // partials ready; all warps done reading act (finished their GEMM)
    const int p0 = (tig & 1) * 4 + (tig >> 1);   // permuted position of col 2*tig in 8-group
#pragma unroll
    for (int mt = 0; mt < 2; mt++) {
        int r0 = wm * 32 + mt * 16 + g, r1 = r0 + 8;
        float su0 = s->ssum[r0][0] + s->ssum[r0][1] + s->ssum[r0][2] + s->ssum[r0][3];
        float sq0 = s->ssq [r0][0] + s->ssq [r0][1] + s->ssq [r0][2] + s->ssq [r0][3];
        float mean0 = su0 * (1.f / 128.f);
        float var0  = sq0 * (1.f / 128.f) - mean0 * mean0;
        float rs0   = rsqrtf(var0 + 1e-5f);
        float su1 = s->ssum[r1][0] + s->ssum[r1][1] + s->ssum[r1][2] + s->ssum[r1][3];
        float sq1 = s->ssq [r1][0] + s->ssq [r1][1] + s->ssq [r1][2] + s->ssq [r1][3];
        float mean1 = su1 * (1.f / 128.f);
        float var1  = sq1 * (1.f / 128.f) - mean1 * mean1;
        float rs1   = rsqrtf(var1 + 1e-5f);
#pragma unroll
        for (int j = 0; j < 4; j++) {
            int c8 = wn * 32 + j * 8;
            float o0 = mish_f((acc[mt][j][0] - mean0) * rs0 * gv[j].x + bb[j].x);
            float o1 = mish_f((acc[mt][j][1] - mean0) * rs0 * gv[j].y + bb[j].y);
            float o2 = mish_f((acc[mt][j][2] - mean1) * rs1 * gv[j].x + bb[j].x);
            float o3 = mish_f((acc[mt][j][3] - mean1) * rs1 * gv[j].y + bb[j].y);
            s->act[r0 * SW + c8 + p0]     = f2tf(o0);
            s->act[r0 * SW + c8 + p0 + 2] = f2tf(o1);
            s->act[r1 * SW + c8 + p0]     = f2tf(o2);
            s->act[r1 * SW + c8 + p0 + 2] = f2tf(o3);
        }
    }
}

// ---- mapping: out = A @ W + bias (fp32 to gmem) ----
__global__ void __launch_bounds__(512, 1) map_kernel(
    const float* __restrict__ A, const uint32_t* __restrict__ Wp,
    const float* __restrict__ bias, float* __restrict__ out, int n)
{
    extern __shared__ char raw[];
    SmemQ* s = (SmemQ*)raw;
    const int tid = threadIdx.x, lane = tid & 31, warp = tid >> 5;
    const int wm = warp >> 2, wn = warp & 3, g = lane >> 2, tig = lane & 3;
    const int row0 = blockIdx.x * 128;
    const uint32_t sw0 = smem_u32(s->w[0]);

    fill_w_async(sw0, Wp, tid);
    fill_act(s, A, row0, n, tid);
    CP_WAIT();
    __syncthreads();

    float acc[2][4][4];
    gemm_core(s, 0, acc, wm, wn, g, tig);

    float2 bv[4];
#pragma unroll
    for (int j = 0; j < 4; j++) bv[j] = *(const float2*)(bias + wn * 32 + j * 8 + 2 * tig);
#pragma unroll
    for (int mt = 0; mt < 2; mt++) {
        int gr0 = row0 + wm * 32 + mt * 16 + g, gr1 = gr0 + 8;
#pragma unroll
        for (int j = 0; j < 4; j++) {
            int cc = wn * 32 + j * 8 + 2 * tig;
            if (gr0 < n)
                *(float2*)(out + (size_t)gr0 * 128 + cc) =
                    make_float2(acc[mt][j][0] + bv[j].x, acc[mt][j][1] + bv[j].y);
            if (gr1 < n)
                *(float2*)(out + (size_t)gr1 * 128 + cc) =
                    make_float2(acc[mt][j][2] + bv[j].x, acc[mt][j][3] + bv[j].y);
        }
    }
}

// ---- fused: segsum( mlp2(A1; a-params) * mlp2(A2; b-params) ) += out ----
__global__ void __launch_bounds__(512, 1) quad_kernel(
    const float* __restrict__ A1, const float* __restrict__ A2,
    const uint32_t* __restrict__ W1a, const float* __restrict__ b1a,
    const float* __restrict__ g1a, const float* __restrict__ n1a,
    const uint32_t* __restrict__ W2a, const float* __restrict__ b2a,
    const uint32_t* __restrict__ W1b, const float* __restrict__ b1b,
    const float* __restrict__ g1b, const float* __restrict__ n1b,
    const uint32_t* __restrict__ W2b, const float* __restrict__ b2b,
    const int* __restrict__ batch, float* __restrict__ out, int n)
{
    extern __shared__ char raw[];
    SmemQ* s = (SmemQ*)raw;
    const int tid = threadIdx.x, lane = tid & 31, warp = tid >> 5;
    const int wm = warp >> 2, wn = warp & 3, g = lane >> 2, tig = lane & 3;
    const int row0 = blockIdx.x * 128;
    const uint32_t sw0 = smem_u32(s->w[0]), sw1 = smem_u32(s->w[1]);

    if (tid < 128) s->sbatch[tid] = (row0 + tid < n) ? batch[row0 + tid] : -1;
    fill_w_async(sw0, W1a, tid);
    fill_act(s, A1, row0, n, tid);
    CP_WAIT();
    __syncthreads();

    float acc[2][4][4];
    // GEMM1 (val h1): A1 @ W1a ; overlap: stream W2a into w[1]
    fill_w_async(sw1, W2a, tid);
    gemm_core(s, 0, acc, wm, wn, g, tig);
    ln_mish_act(s, acc, b1a, g1a, n1a, wm, wn, g, tig);
    CP_WAIT();
    __syncthreads();

    // GEMM2 (val out): h1v @ W2a ; overlap: stream W1b into w[0]
    fill_w_async(sw0, W1b, tid);
    gemm_core(s, 1, acc, wm, wn, g, tig);

    float vv[2][4][4];
    {
        float2 b2[4];
#pragma unroll
        for (int j = 0; j < 4; j++) b2[j] = *(const float2*)(b2a + wn * 32 + j * 8 + 2 * tig);
#pragma unroll
        for (int mt = 0; mt < 2; mt++)
#pragma unroll
            for (int j = 0; j < 4; j++) {
                vv[mt][j][0] = acc[mt][j][0] + b2[j].x;
                vv[mt][j][1] = acc[mt][j][1] + b2[j].y;
                vv[mt][j][2] = acc[mt][j][2] + b2[j].x;
                vv[mt][j][3] = acc[mt][j][3] + b2[j].y;
            }
    }
    __syncthreads();                 // all warps done reading act (h1v)

    // key side
    fill_act(s, A2, row0, n, tid);
    CP_WAIT();
    __syncthreads();

    // GEMM3 (key h1): A2 @ W1b ; overlap: stream W2b into w[1]
    fill_w_async(sw1, W2b, tid);
    gemm_core(s, 0, acc, wm, wn, g, tig);
    ln_mish_act(s, acc, b1b, g1b, n1b, wm, wn, g, tig);
    CP_WAIT();
    __syncthreads();

    // GEMM4 (key out): h1k @ W2b
    gemm_core(s, 1, acc, wm, wn, g, tig);
    __syncthreads();                 // all warps done reading act (h1k)

    // y = (kq + b2b) * vv -> act (plain float, stride SW)
    {
        float2 b2[4];
#pragma unroll
        for (int j = 0; j < 4; j++) b2[j] = *(const float2*)(b2b + wn * 32 + j * 8 + 2 * tig);
        float* Y = (float*)s->act;
#pragma unroll
        for (int mt = 0; mt < 2; mt++) {
            int r0 = wm * 32 + mt * 16 + g, r1 = r0 + 8;
#pragma unroll
            for (int j = 0; j < 4; j++) {
                int cc = wn * 32 + j * 8 + 2 * tig;
                Y[r0 * SW + cc]     = (acc[mt][j][0] + b2[j].x) * vv[mt][j][0];
                Y[r0 * SW + cc + 1] = (acc[mt][j][1] + b2[j].y) * vv[mt][j][1];
                Y[r1 * SW + cc]     = (acc[mt][j][2] + b2[j].x) * vv[mt][j][2];
                Y[r1 * SW + cc + 1] = (acc[mt][j][3] + b2[j].y) * vv[mt][j][3];
            }
        }
    }
    __syncthreads();

    // per-block run-length segment reduction + atomicAdd (4 x 32-row strips)
    {
        const float* Y = (const float*)s->act;
        int c = tid & 127, qq = tid >> 7;
        int r = qq * 32;
        float a = 0.f;
        int cur = s->sbatch[r];
#pragma unroll 4
        for (int i = 0; i < 32; i++, r++) {
            int sbv = s->sbatch[r];
            if (sbv != cur) {
                if (cur >= 0) atomicAdd(out + (size_t)cur * 128 + c, a);
                a = 0.f; cur = sbv;
            }
            a += Y[r * SW + c];
        }
        if (cur >= 0) atomicAdd(out + (size_t)cur * 128 + c, a);
    }
}

// ---- per-segment, per-feature softmax, online, in place ----
__global__ void __launch_bounds__(128) seg_softmax_kernel(
    float* __restrict__ io, const int* __restrict__ segstart)
{
    int b = blockIdx.x;
    int s0 = segstart[b], e = segstart[b + 1];
    int t = threadIdx.x;
    if (s0 >= e) return;
    float m = -3.4e38f, d = 0.f;
    for (int r = s0; r < e; r++) {
        float v = io[(size_t)r * 128 + t];
        float nm = fmaxf(m, v);
        d = d * __expf(m - nm) + __expf(v - nm);
        m = nm;
    }
    float inv = 1.f / d;
    for (int r = s0; r < e; r++) {
        float v = io[(size_t)r * 128 + t];
        io[(size_t)r * 128 + t] = __expf(v - m) * inv;
    }
}

extern "C" void kernel_launch(void* const* d_in, const int* in_sizes, int n_in,
                              void* d_out, int out_size)
{
    const float* x     = (const float*)d_in[0];
    const int*   batch = (const int*)  d_in[1];
    const float* W_map = (const float*)d_in[3];
    const float* b_map = (const float*)d_in[4];
    const float* kW1 = (const float*)d_in[5],  *kb1 = (const float*)d_in[6];
    const float* kg  = (const float*)d_in[7],  *kbn = (const float*)d_in[8];
    const float* kW2 = (const float*)d_in[9],  *kb2 = (const float*)d_in[10];
    const float* vW1 = (const float*)d_in[11], *vb1 = (const float*)d_in[12];
    const float* vg  = (const float*)d_in[13], *vbn = (const float*)d_in[14];
    const float* vW2 = (const float*)d_in[15], *vb2 = (const float*)d_in[16];
    const float* iW_map = (const float*)d_in[17], *ib_map = (const float*)d_in[18];
    const float* ikW1 = (const float*)d_in[19], *ikb1 = (const float*)d_in[20];
    const float* ikg  = (const float*)d_in[21], *ikbn = (const float*)d_in[22];
    const float* ikW2 = (const float*)d_in[23], *ikb2 = (const float*)d_in[24];
    const float* ivW1 = (const float*)d_in[25], *ivb1 = (const float*)d_in[26];
    const float* ivg  = (const float*)d_in[27], *ivbn = (const float*)d_in[28];
    const float* ivW2 = (const float*)d_in[29], *ivb2 = (const float*)d_in[30];

    int n = in_sizes[0] / 128;
    float* out = (float*)d_out;

    float *keys, *k2; int* segstart; uint32_t* wprep;
    cudaGetSymbolAddress((void**)&keys, g_keys);
    cudaGetSymbolAddress((void**)&k2,   g_k2);
    cudaGetSymbolAddress((void**)&segstart, g_segstart);
    cudaGetSymbolAddress((void**)&wprep, g_wprep);

    const int SMB = (int)sizeof(SmemQ);
    cudaFuncSetAttribute(map_kernel,  cudaFuncAttributeMaxDynamicSharedMemorySize, SMB);
    cudaFuncSetAttribute(quad_kernel, cudaFuncAttributeMaxDynamicSharedMemorySize, SMB);

    cudaMemsetAsync(d_out, 0, (size_t)out_size * sizeof(float));
    segstart_kernel<<<(NBATCH + 256) / 256, 256>>>(batch, n, segstart);
    // weight slots: 0=W_map 1=kW1 2=kW2 3=vW1 4=vW2 5=iW_map 6=ikW1 7=ikW2 8=ivW1 9=ivW2
    prep_all<<<dim3(64, 10), 256>>>(W_map, kW1, kW2, vW1, vW2, iW_map, ikW1, ikW2, ivW1, ivW2);

    int mb = (n + 127) / 128;
#define WSLOT(i) (wprep + (size_t)(i) * WROW_WORDS)

    // outer encoder
    map_kernel<<<mb, 512, SMB>>>(x, WSLOT(0), b_map, keys, n);
    seg_softmax_kernel<<<NBATCH, 128>>>(keys, segstart);
    quad_kernel<<<mb, 512, SMB>>>(x, keys,
                                  WSLOT(3), vb1, vg, vbn, WSLOT(4), vb2,
                                  WSLOT(1), kb1, kg, kbn, WSLOT(2), kb2,
                                  batch, out, n);

    // inner encoder on keys
    map_kernel<<<mb, 512, SMB>>>(keys, WSLOT(5), ib_map, k2, n);
    seg_softmax_kernel<<<NBATCH, 128>>>(k2, segstart);
    quad_kernel<<<mb, 512, SMB>>>(keys, k2,
                                  WSLOT(8), ivb1, ivg, ivbn, WSLOT(9), ivb2,
                                  WSLOT(6), ikb1, ikg, ikbn, WSLOT(7), ikb2,
                                  batch, out + (size_t)NBATCH * 128, n);
}

// round 9
// speedup vs baseline: 1.2973x; 1.2973x over previous
#include <cuda_runtime.h>
#include <math.h>
#include <stdint.h>

#define MAXN   500000
#define NBATCH 4096

// ---- static scratch ----
__device__ __align__(16) float g_keys[(size_t)MAXN * 128];   // raw key0 (pre-softmax)
__device__ __align__(16) float g_k2  [(size_t)MAXN * 128];   // raw key0b (pre-softmax)
__device__ __align__(16) float g_m1 [NBATCH * 128];
__device__ __align__(16) float g_id1[NBATCH * 128];
__device__ __align__(16) float g_m2 [NBATCH * 128];
__device__ __align__(16) float g_id2[NBATCH * 128];
__device__ int g_segstart[NBATCH + 1];

struct SmemQ {
    uint32_t act[128][132];      // operand tile (tf32); reused as y (float, stride 132)
    uint32_t bs[2][32][136];     // double-buffered W chunk (tf32)
    float    ssum[128][4];
    float    ssq [128][4];
    int      sbatch[128];
};

__device__ __forceinline__ float mish_f(float x) {
    float sp = (x > 20.f) ? x : log1pf(__expf(x));
    return x * tanhf(sp);
}
__device__ __forceinline__ uint32_t f2tf(float f) {
    uint32_t u; asm("cvt.rna.tf32.f32 %0, %1;" : "=r"(u) : "f"(f)); return u;
}
__device__ __forceinline__ void mma8(float c[4], const uint32_t a[4], const uint32_t b[2]) {
    asm volatile("mma.sync.aligned.m16n8k8.row.col.f32.tf32.tf32.f32 "
        "{%0,%1,%2,%3},{%4,%5,%6,%7},{%8,%9},{%0,%1,%2,%3};"
        : "+f"(c[0]), "+f"(c[1]), "+f"(c[2]), "+f"(c[3])
        : "r"(a[0]), "r"(a[1]), "r"(a[2]), "r"(a[3]), "r"(b[0]), "r"(b[1]));
}

// ---- segment starts via binary search over sorted batch ----
__global__ void segstart_kernel(const int* __restrict__ batch, int n, int* __restrict__ segstart) {
    int b = blockIdx.x * blockDim.x + threadIdx.x;
    if (b > NBATCH) return;
    int lo = 0, hi = n;
    while (lo < hi) { int m = (lo + hi) >> 1; if (batch[m] < b) lo = m + 1; else hi = m; }
    segstart[b] = lo;
}

// ---- one-pass segment reduce: per (segment, feature) max and 1/sum(exp) ----
__global__ void __launch_bounds__(128) seg_reduce_kernel(
    const float* __restrict__ in, const int* __restrict__ segstart,
    float* __restrict__ M, float* __restrict__ ID)
{
    int b = blockIdx.x;
    int s0 = segstart[b], e = segstart[b + 1];
    int t = threadIdx.x;
    if (s0 >= e) {
        M[(size_t)b * 128 + t] = 0.f; ID[(size_t)b * 128 + t] = 0.f;
        return;
    }
    float m0 = -3.4e38f, m1 = -3.4e38f, m2 = -3.4e38f, m3 = -3.4e38f;
    float d0 = 0.f, d1 = 0.f, d2 = 0.f, d3 = 0.f;
    int r = s0;
    for (; r + 3 < e; r += 4) {
        float v0 = in[(size_t)(r + 0) * 128 + t];
        float v1 = in[(size_t)(r + 1) * 128 + t];
        float v2 = in[(size_t)(r + 2) * 128 + t];
        float v3 = in[(size_t)(r + 3) * 128 + t];
        float n0 = fmaxf(m0, v0); d0 = d0 * __expf(m0 - n0) + __expf(v0 - n0); m0 = n0;
        float n1 = fmaxf(m1, v1); d1 = d1 * __expf(m1 - n1) + __expf(v1 - n1); m1 = n1;
        float n2 = fmaxf(m2, v2); d2 = d2 * __expf(m2 - n2) + __expf(v2 - n2); m2 = n2;
        float n3 = fmaxf(m3, v3); d3 = d3 * __expf(m3 - n3) + __expf(v3 - n3); m3 = n3;
    }
    for (; r < e; r++) {
        float v = in[(size_t)r * 128 + t];
        float nm = fmaxf(m0, v); d0 = d0 * __expf(m0 - nm) + __expf(v - nm); m0 = nm;
    }
    float mm = fmaxf(fmaxf(m0, m1), fmaxf(m2, m3));
    float dd = d0 * __expf(m0 - mm) + d1 * __expf(m1 - mm)
             + d2 * __expf(m2 - mm) + d3 * __expf(m3 - mm);
    M [(size_t)b * 128 + t] = mm;
    ID[(size_t)b * 128 + t] = 1.f / dd;
}

// ---- load 128x128 fp32 tile -> smem act (tf32); optional on-the-fly softmax norm ----
// Requires s->sbatch valid (synced) when M != nullptr.
__device__ __forceinline__ void fill_act(SmemQ* s, const float* __restrict__ src,
                                         int row0, int n, int tid,
                                         const float* __restrict__ M,
                                         const float* __restrict__ ID) {
#pragma unroll
    for (int i = 0; i < 8; i++) {
        int e = tid + i * 512;
        int r = e >> 5, k4 = (e & 31) * 4;
        int gr = row0 + r;
        float4 v = make_float4(0.f, 0.f, 0.f, 0.f);
        if (gr < n) {
            v = *(const float4*)(src + (size_t)gr * 128 + k4);
            if (M) {
                int b = s->sbatch[r];
                float4 mv = *(const float4*)(M  + (size_t)b * 128 + k4);
                float4 iv = *(const float4*)(ID + (size_t)b * 128 + k4);
                v.x = __expf(v.x - mv.x) * iv.x;
                v.y = __expf(v.y - mv.y) * iv.y;
                v.z = __expf(v.z - mv.z) * iv.z;
                v.w = __expf(v.w - mv.w) * iv.w;
            }
        }
        s->act[r][k4 + 0] = f2tf(v.x);
        s->act[r][k4 + 1] = f2tf(v.y);
        s->act[r][k4 + 2] = f2tf(v.z);
        s->act[r][k4 + 3] = f2tf(v.w);
    }
}

// ---- GEMM: acc = act(smem) @ W(gmem streamed, reg-prefetch double buffer) ----
// 16 warps, warp tile 32x32: rows wm*32+mt*16+g(+8), cols wn*32+j*8+2tig(+1)
__device__ __forceinline__ void gemm_act_W(SmemQ* s, const float* __restrict__ W,
                                           float acc[2][4][4],
                                           int wm, int wn, int g, int tig, int tid) {
    const int kw = tid >> 4, cw = (tid & 15) * 8;
#pragma unroll
    for (int mt = 0; mt < 2; mt++)
#pragma unroll
        for (int j = 0; j < 4; j++)
#pragma unroll
            for (int c = 0; c < 4; c++) acc[mt][j][c] = 0.f;

    float4 p0 = *(const float4*)(W + (size_t)kw * 128 + cw);
    float4 p1 = *(const float4*)(W + (size_t)kw * 128 + cw + 4);
    s->bs[0][kw][cw + 0] = f2tf(p0.x); s->bs[0][kw][cw + 1] = f2tf(p0.y);
    s->bs[0][kw][cw + 2] = f2tf(p0.z); s->bs[0][kw][cw + 3] = f2tf(p0.w);
    s->bs[0][kw][cw + 4] = f2tf(p1.x); s->bs[0][kw][cw + 5] = f2tf(p1.y);
    s->bs[0][kw][cw + 6] = f2tf(p1.z); s->bs[0][kw][cw + 7] = f2tf(p1.w);
    __syncthreads();

#pragma unroll
    for (int c = 0; c < 4; c++) {
        if (c < 3) {
            p0 = *(const float4*)(W + (size_t)((c + 1) * 32 + kw) * 128 + cw);
            p1 = *(const float4*)(W + (size_t)((c + 1) * 32 + kw) * 128 + cw + 4);
        }
        const int buf = c & 1;
#pragma unroll
        for (int kk = 0; kk < 4; kk++) {
            const int ka = c * 32 + kk * 8, kb = kk * 8;
            uint32_t af[2][4], bf[4][2];
#pragma unroll
            for (int mt = 0; mt < 2; mt++) {
                int r = wm * 32 + mt * 16 + g;
                af[mt][0] = s->act[r][ka + tig];
                af[mt][1] = s->act[r + 8][ka + tig];
                af[mt][2] = s->act[r][ka + tig + 4];
                af[mt][3] = s->act[r + 8][ka + tig + 4];
            }
#pragma unroll
            for (int j = 0; j < 4; j++) {
                int nn = wn * 32 + j * 8 + g;
                bf[j][0] = s->bs[buf][kb + tig][nn];
                bf[j][1] = s->bs[buf][kb + tig + 4][nn];
            }
#pragma unroll
            for (int mt = 0; mt < 2; mt++)
#pragma unroll
                for (int j = 0; j < 4; j++) mma8(acc[mt][j], af[mt], bf[j]);
        }
        if (c < 3) {
            __syncthreads();
            const int nb = (c + 1) & 1;
            s->bs[nb][kw][cw + 0] = f2tf(p0.x); s->bs[nb][kw][cw + 1] = f2tf(p0.y);
            s->bs[nb][kw][cw + 2] = f2tf(p0.z); s->bs[nb][kw][cw + 3] = f2tf(p0.w);
            s->bs[nb][kw][cw + 4] = f2tf(p1.x); s->bs[nb][kw][cw + 5] = f2tf(p1.y);
            s->bs[nb][kw][cw + 6] = f2tf(p1.z); s->bs[nb][kw][cw + 7] = f2tf(p1.w);
            __syncthreads();
        }
    }
}

// ---- bias + layernorm + mish on acc, write result (tf32) back into act ----
__device__ __forceinline__ void ln_mish_act(SmemQ* s, float acc[2][4][4],
    const float* __restrict__ bias, const float* __restrict__ gam, const float* __restrict__ bet,
    int wm, int wn, int g, int tig)
{
    float2 bv[4], gv[4], bb[4];
#pragma unroll
    for (int j = 0; j < 4; j++) {
        int cc = wn * 32 + j * 8 + 2 * tig;
        bv[j] = *(const float2*)(bias + cc);
        gv[j] = *(const float2*)(gam + cc);
        bb[j] = *(const float2*)(bet + cc);
    }
#pragma unroll
    for (int mt = 0; mt < 2; mt++) {
        float s0 = 0.f, q0 = 0.f, s1 = 0.f, q1 = 0.f;
#pragma unroll
        for (int j = 0; j < 4; j++) {
            float a0 = acc[mt][j][0] + bv[j].x, a1 = acc[mt][j][1] + bv[j].y;
            float a2 = acc[mt][j][2] + bv[j].x, a3 = acc[mt][j][3] + bv[j].y;
            acc[mt][j][0] = a0; acc[mt][j][1] = a1; acc[mt][j][2] = a2; acc[mt][j][3] = a3;
            s0 += a0 + a1; q0 += a0 * a0 + a1 * a1;
            s1 += a2 + a3; q1 += a2 * a2 + a3 * a3;
        }
#pragma unroll
        for (int o = 1; o <= 2; o <<= 1) {
            s0 += __shfl_xor_sync(0xffffffffu, s0, o);
            q0 += __shfl_xor_sync(0xffffffffu, q0, o);
            s1 += __shfl_xor_sync(0xffffffffu, s1, o);
            q1 += __shfl_xor_sync(0xffffffffu, q1, o);
        }
        if (tig == 0) {
            int r = wm * 32 + mt * 16 + g;
            s->ssum[r][wn] = s0; s->ssq[r][wn] = q0;
            s->ssum[r + 8][wn] = s1; s->ssq[r + 8][wn] = q1;
        }
    }
    __syncthreads();   // partials ready; all warps done reading act
#pragma unroll
    for (int mt = 0; mt < 2; mt++) {
        int r0 = wm * 32 + mt * 16 + g, r1 = r0 + 8;
        float su0 = s->ssum[r0][0] + s->ssum[r0][1] + s->ssum[r0][2] + s->ssum[r0][3];
        float sq0 = s->ssq [r0][0] + s->ssq [r0][1] + s->ssq [r0][2] + s->ssq [r0][3];
        float mean0 = su0 * (1.f / 128.f);
        float var0  = sq0 * (1.f / 128.f) - mean0 * mean0;
        float rs0   = rsqrtf(var0 + 1e-5f);
        float su1 = s->ssum[r1][0] + s->ssum[r1][1] + s->ssum[r1][2] + s->ssum[r1][3];
        float sq1 = s->ssq [r1][0] + s->ssq [r1][1] + s->ssq [r1][2] + s->ssq [r1][3];
        float mean1 = su1 * (1.f / 128.f);
        float var1  = sq1 * (1.f / 128.f) - mean1 * mean1;
        float rs1   = rsqrtf(var1 + 1e-5f);
#pragma unroll
        for (int j = 0; j < 4; j++) {
            int cc = wn * 32 + j * 8 + 2 * tig;
            float o0 = mish_f((acc[mt][j][0] - mean0) * rs0 * gv[j].x + bb[j].x);
            float o1 = mish_f((acc[mt][j][1] - mean0) * rs0 * gv[j].y + bb[j].y);
            float o2 = mish_f((acc[mt][j][2] - mean1) * rs1 * gv[j].x + bb[j].x);
            float o3 = mish_f((acc[mt][j][3] - mean1) * rs1 * gv[j].y + bb[j].y);
            s->act[r0][cc] = f2tf(o0); s->act[r0][cc + 1] = f2tf(o1);
            s->act[r1][cc] = f2tf(o2); s->act[r1][cc + 1] = f2tf(o3);
        }
    }
    __syncthreads();
}

// ---- mapping: out = norm?(A) @ W + bias (fp32 to gmem) ----
__global__ void __launch_bounds__(512, 1) map_kernel(
    const float* __restrict__ A, const float* __restrict__ W,
    const float* __restrict__ bias, float* __restrict__ out, int n,
    const int* __restrict__ batch,
    const float* __restrict__ M, const float* __restrict__ ID)
{
    extern __shared__ char raw[];
    SmemQ* s = (SmemQ*)raw;
    const int tid = threadIdx.x, lane = tid & 31, warp = tid >> 5;
    const int wm = warp >> 2, wn = warp & 3, g = lane >> 2, tig = lane & 3;
    const int row0 = blockIdx.x * 128;

    if (M) {
        if (tid < 128) s->sbatch[tid] = (row0 + tid < n) ? batch[row0 + tid] : -1;
        __syncthreads();
    }
    fill_act(s, A, row0, n, tid, M, ID);
    float acc[2][4][4];
    gemm_act_W(s, W, acc, wm, wn, g, tig, tid);

    float2 bv[4];
#pragma unroll
    for (int j = 0; j < 4; j++) bv[j] = *(const float2*)(bias + wn * 32 + j * 8 + 2 * tig);
#pragma unroll
    for (int mt = 0; mt < 2; mt++) {
        int gr0 = row0 + wm * 32 + mt * 16 + g, gr1 = gr0 + 8;
#pragma unroll
        for (int j = 0; j < 4; j++) {
            int cc = wn * 32 + j * 8 + 2 * tig;
            if (gr0 < n)
                *(float2*)(out + (size_t)gr0 * 128 + cc) =
                    make_float2(acc[mt][j][0] + bv[j].x, acc[mt][j][1] + bv[j].y);
            if (gr1 < n)
                *(float2*)(out + (size_t)gr1 * 128 + cc) =
                    make_float2(acc[mt][j][2] + bv[j].x, acc[mt][j][3] + bv[j].y);
        }
    }
}

// ---- fused: segsum( mlp2(norm?(A1); a) * mlp2(norm?(A2); b) ) += out ----
__global__ void __launch_bounds__(512, 1) quad_kernel(
    const float* __restrict__ A1, const float* __restrict__ A2,
    const float* __restrict__ W1a, const float* __restrict__ b1a,
    const float* __restrict__ g1a, const float* __restrict__ n1a,
    const float* __restrict__ W2a, const float* __restrict__ b2a,
    const float* __restrict__ W1b, const float* __restrict__ b1b,
    const float* __restrict__ g1b, const float* __restrict__ n1b,
    const float* __restrict__ W2b, const float* __restrict__ b2b,
    const int* __restrict__ batch, float* __restrict__ out, int n,
    const float* __restrict__ M1, const float* __restrict__ ID1,   // norm for A1 (or null)
    const float* __restrict__ M2, const float* __restrict__ ID2)   // norm for A2 (or null)
{
    extern __shared__ char raw[];
    SmemQ* s = (SmemQ*)raw;
    const int tid = threadIdx.x, lane = tid & 31, warp = tid >> 5;
    const int wm = warp >> 2, wn = warp & 3, g = lane >> 2, tig = lane & 3;
    const int row0 = blockIdx.x * 128;

    if (tid < 128) s->sbatch[tid] = (row0 + tid < n) ? batch[row0 + tid] : -1;
    __syncthreads();
    fill_act(s, A1, row0, n, tid, M1, ID1);

    float acc[2][4][4];
    // val side: h1v = LN/mish(A1@W1a + b1a); v = h1v@W2a + b2a (in regs)
    gemm_act_W(s, W1a, acc, wm, wn, g, tig, tid);
    ln_mish_act(s, acc, b1a, g1a, n1a, wm, wn, g, tig);
    gemm_act_W(s, W2a, acc, wm, wn, g, tig, tid);

    float vv[2][4][4];
    {
        float2 b2[4];
#pragma unroll
        for (int j = 0; j < 4; j++) b2[j] = *(const float2*)(b2a + wn * 32 + j * 8 + 2 * tig);
#pragma unroll
        for (int mt = 0; mt < 2; mt++)
#pragma unroll
            for (int j = 0; j < 4; j++) {
                vv[mt][j][0] = acc[mt][j][0] + b2[j].x;
                vv[mt][j][1] = acc[mt][j][1] + b2[j].y;
                vv[mt][j][2] = acc[mt][j][2] + b2[j].x;
                vv[mt][j][3] = acc[mt][j][3] + b2[j].y;
            }
    }
    __syncthreads();                 // all warps done reading act (h1v)

    // key side: kq = mlp2(A2); y = kq * v
    fill_act(s, A2, row0, n, tid, M2, ID2);
    gemm_act_W(s, W1b, acc, wm, wn, g, tig, tid);
    ln_mish_act(s, acc, b1b, g1b, n1b, wm, wn, g, tig);
    gemm_act_W(s, W2b, acc, wm, wn, g, tig, tid);
    __syncthreads();                 // all warps done reading act (h1k)

    {
        float2 b2[4];
#pragma unroll
        for (int j = 0; j < 4; j++) b2[j] = *(const float2*)(b2b + wn * 32 + j * 8 + 2 * tig);
        float* Y = (float*)s->act;
#pragma unroll
        for (int mt = 0; mt < 2; mt++) {
            int r0 = wm * 32 + mt * 16 + g, r1 = r0 + 8;
#pragma unroll
            for (int j = 0; j < 4; j++) {
                int cc = wn * 32 + j * 8 + 2 * tig;
                Y[r0 * 132 + cc]     = (acc[mt][j][0] + b2[j].x) * vv[mt][j][0];
                Y[r0 * 132 + cc + 1] = (acc[mt][j][1] + b2[j].y) * vv[mt][j][1];
                Y[r1 * 132 + cc]     = (acc[mt][j][2] + b2[j].x) * vv[mt][j][2];
                Y[r1 * 132 + cc + 1] = (acc[mt][j][3] + b2[j].y) * vv[mt][j][3];
            }
        }
    }
    __syncthreads();

    // per-block run-length segment reduction + atomicAdd (4 x 32-row strips)
    {
        const float* Y = (const float*)s->act;
        int c = tid & 127, qq = tid >> 7;
        int r = qq * 32;
        float a = 0.f;
        int cur = s->sbatch[r];
#pragma unroll 4
        for (int i = 0; i < 32; i++, r++) {
            int sbv = s->sbatch[r];
            if (sbv != cur) {
                if (cur >= 0) atomicAdd(out + (size_t)cur * 128 + c, a);
                a = 0.f; cur = sbv;
            }
            a += Y[r * 132 + c];
        }
        if (cur >= 0) atomicAdd(out + (size_t)cur * 128 + c, a);
    }
}

extern "C" void kernel_launch(void* const* d_in, const int* in_sizes, int n_in,
                              void* d_out, int out_size)
{
    const float* x     = (const float*)d_in[0];
    const int*   batch = (const int*)  d_in[1];
    const float* W_map = (const float*)d_in[3];
    const float* b_map = (const float*)d_in[4];
    const float* kW1 = (const float*)d_in[5],  *kb1 = (const float*)d_in[6];
    const float* kg  = (const float*)d_in[7],  *kbn = (const float*)d_in[8];
    const float* kW2 = (const float*)d_in[9],  *kb2 = (const float*)d_in[10];
    const float* vW1 = (const float*)d_in[11], *vb1 = (const float*)d_in[12];
    const float* vg  = (const float*)d_in[13], *vbn = (const float*)d_in[14];
    const float* vW2 = (const float*)d_in[15], *vb2 = (const float*)d_in[16];
    const float* iW_map = (const float*)d_in[17], *ib_map = (const float*)d_in[18];
    const float* ikW1 = (const float*)d_in[19], *ikb1 = (const float*)d_in[20];
    const float* ikg  = (const float*)d_in[21], *ikbn = (const float*)d_in[22];
    const float* ikW2 = (const float*)d_in[23], *ikb2 = (const float*)d_in[24];
    const float* ivW1 = (const float*)d_in[25], *ivb1 = (const float*)d_in[26];
    const float* ivg  = (const float*)d_in[27], *ivbn = (const float*)d_in[28];
    const float* ivW2 = (const float*)d_in[29], *ivb2 = (const float*)d_in[30];

    int n = in_sizes[0] / 128;
    float* out = (float*)d_out;

    float *key0, *key0b, *m1, *id1, *m2, *id2; int* segstart;
    cudaGetSymbolAddress((void**)&key0,  g_keys);
    cudaGetSymbolAddress((void**)&key0b, g_k2);
    cudaGetSymbolAddress((void**)&m1,  g_m1);
    cudaGetSymbolAddress((void**)&id1, g_id1);
    cudaGetSymbolAddress((void**)&m2,  g_m2);
    cudaGetSymbolAddress((void**)&id2, g_id2);
    cudaGetSymbolAddress((void**)&segstart, g_segstart);

    const int SMB = (int)sizeof(SmemQ);
    cudaFuncSetAttribute(map_kernel,  cudaFuncAttributeMaxDynamicSharedMemorySize, SMB);
    cudaFuncSetAttribute(quad_kernel, cudaFuncAttributeMaxDynamicSharedMemorySize, SMB);

    cudaMemsetAsync(d_out, 0, (size_t)out_size * sizeof(float));
    segstart_kernel<<<(NBATCH + 256) / 256, 256>>>(batch, n, segstart);

    int mb = (n + 127) / 128;

    // outer encoder: key0 = x@W_map + b; (m1,id1) = seg softmax stats of key0
    map_kernel<<<mb, 512, SMB>>>(x, W_map, b_map, key0, n, batch, nullptr, nullptr);
    seg_reduce_kernel<<<NBATCH, 128>>>(key0, segstart, m1, id1);
    quad_kernel<<<mb, 512, SMB>>>(x, key0,
                                  vW1, vb1, vg, vbn, vW2, vb2,
                                  kW1, kb1, kg, kbn, kW2, kb2,
                                  batch, out, n,
                                  nullptr, nullptr, m1, id1);

    // inner encoder: keys = norm(key0); key0b = keys@iW_map + b; stats (m2,id2)
    map_kernel<<<mb, 512, SMB>>>(key0, iW_map, ib_map, key0b, n, batch, m1, id1);
    seg_reduce_kernel<<<NBATCH, 128>>>(key0b, segstart, m2, id2);
    quad_kernel<<<mb, 512, SMB>>>(key0, key0b,
                                  ivW1, ivb1, ivg, ivbn, ivW2, ivb2,
                                  ikW1, ikb1, ikg, ikbn, ikW2, ikb2,
                                  batch, out + (size_t)NBATCH * 128, n,
                                  m1, id1, m2, id2);
}

// round 10
// speedup vs baseline: 1.3548x; 1.0443x over previous
#include <cuda_runtime.h>
#include <math.h>
#include <stdint.h>

#define MAXN   500000
#define NBATCH 4096
#define BR     64          // block rows per CTA

// ---- static scratch ----
__device__ __align__(16) float g_keys[(size_t)MAXN * 128];
__device__ __align__(16) float g_k2  [(size_t)MAXN * 128];
__device__ int g_segstart[NBATCH + 1];

struct SmemQ {
    uint32_t act[BR][132];       // operand tile (tf32); reused as y (float, stride 132)
    uint32_t bs[2][32][136];     // double-buffered W chunk (tf32)
    float    ssum[BR][4];
    float    ssq [BR][4];
    int      sbatch[BR];
};

__device__ __forceinline__ float mish_f(float x) {
    float sp = (x > 20.f) ? x : log1pf(__expf(x));
    return x * tanhf(sp);
}
__device__ __forceinline__ uint32_t f2tf(float f) {
    uint32_t u; asm("cvt.rna.tf32.f32 %0, %1;" : "=r"(u) : "f"(f)); return u;
}
__device__ __forceinline__ void mma8(float c[4], const uint32_t a[4], const uint32_t b[2]) {
    asm volatile("mma.sync.aligned.m16n8k8.row.col.f32.tf32.tf32.f32 "
        "{%0,%1,%2,%3},{%4,%5,%6,%7},{%8,%9},{%0,%1,%2,%3};"
        : "+f"(c[0]), "+f"(c[1]), "+f"(c[2]), "+f"(c[3])
        : "r"(a[0]), "r"(a[1]), "r"(a[2]), "r"(a[3]), "r"(b[0]), "r"(b[1]));
}

// ---- segment starts via binary search over sorted batch ----
__global__ void segstart_kernel(const int* __restrict__ batch, int n, int* __restrict__ segstart) {
    int b = blockIdx.x * blockDim.x + threadIdx.x;
    if (b > NBATCH) return;
    int lo = 0, hi = n;
    while (lo < hi) { int m = (lo + hi) >> 1; if (batch[m] < b) lo = m + 1; else hi = m; }
    segstart[b] = lo;
}

// ---- per-segment, per-feature softmax, online, in place ----
__global__ void __launch_bounds__(128) seg_softmax_kernel(
    float* __restrict__ io, const int* __restrict__ segstart)
{
    int b = blockIdx.x;
    int s0 = segstart[b], e = segstart[b + 1];
    int t = threadIdx.x;
    if (s0 >= e) return;
    float m = -3.4e38f, d = 0.f;
    for (int r = s0; r < e; r++) {
        float v = io[(size_t)r * 128 + t];
        float nm = fmaxf(m, v);
        d = d * __expf(m - nm) + __expf(v - nm);
        m = nm;
    }
    float inv = 1.f / d;
    for (int r = s0; r < e; r++) {
        float v = io[(size_t)r * 128 + t];
        io[(size_t)r * 128 + t] = __expf(v - m) * inv;
    }
}

// ---- load BRx128 fp32 tile -> smem act (tf32), zero-padded past n. 256 threads ----
__device__ __forceinline__ void fill_act(SmemQ* s, const float* __restrict__ src,
                                         int row0, int n, int tid) {
#pragma unroll
    for (int i = 0; i < 8; i++) {
        int e = tid + i * 256;
        int r = e >> 5, k4 = (e & 31) * 4;
        int gr = row0 + r;
        float4 v = make_float4(0.f, 0.f, 0.f, 0.f);
        if (gr < n) v = *(const float4*)(src + (size_t)gr * 128 + k4);
        s->act[r][k4 + 0] = f2tf(v.x);
        s->act[r][k4 + 1] = f2tf(v.y);
        s->act[r][k4 + 2] = f2tf(v.z);
        s->act[r][k4 + 3] = f2tf(v.w);
    }
}

// ---- GEMM: acc = act(smem, BRx128) @ W(gmem streamed, reg-prefetch double buffer) ----
// 8 warps, warp tile 32x32: rows wm*32+mt*16+g(+8) (wm 0..1), cols wn*32+j*8+2tig(+1) (wn 0..3)
__device__ __forceinline__ void gemm_act_W(SmemQ* s, const float* __restrict__ W,
                                           float acc[2][4][4],
                                           int wm, int wn, int g, int tig, int tid) {
    const int kw = tid >> 4;            // 0..15 (handles rows kw and kw+16)
    const int cw = (tid & 15) * 8;
#pragma unroll
    for (int mt = 0; mt < 2; mt++)
#pragma unroll
        for (int j = 0; j < 4; j++)
#pragma unroll
            for (int c = 0; c < 4; c++) acc[mt][j][c] = 0.f;

    float4 p[2][2];
#pragma unroll
    for (int h = 0; h < 2; h++) {
        p[h][0] = *(const float4*)(W + (size_t)(kw + 16 * h) * 128 + cw);
        p[h][1] = *(const float4*)(W + (size_t)(kw + 16 * h) * 128 + cw + 4);
    }
#pragma unroll
    for (int h = 0; h < 2; h++) {
        int rw = kw + 16 * h;
        s->bs[0][rw][cw + 0] = f2tf(p[h][0].x); s->bs[0][rw][cw + 1] = f2tf(p[h][0].y);
        s->bs[0][rw][cw + 2] = f2tf(p[h][0].z); s->bs[0][rw][cw + 3] = f2tf(p[h][0].w);
        s->bs[0][rw][cw + 4] = f2tf(p[h][1].x); s->bs[0][rw][cw + 5] = f2tf(p[h][1].y);
        s->bs[0][rw][cw + 6] = f2tf(p[h][1].z); s->bs[0][rw][cw + 7] = f2tf(p[h][1].w);
    }
    __syncthreads();

#pragma unroll
    for (int c = 0; c < 4; c++) {
        if (c < 3) {
#pragma unroll
            for (int h = 0; h < 2; h++) {
                p[h][0] = *(const float4*)(W + (size_t)((c + 1) * 32 + kw + 16 * h) * 128 + cw);
                p[h][1] = *(const float4*)(W + (size_t)((c + 1) * 32 + kw + 16 * h) * 128 + cw + 4);
            }
        }
        const int buf = c & 1;
#pragma unroll
        for (int kk = 0; kk < 4; kk++) {
            const int ka = c * 32 + kk * 8, kb = kk * 8;
            uint32_t af[2][4], bf[4][2];
#pragma unroll
            for (int mt = 0; mt < 2; mt++) {
                int r = wm * 32 + mt * 16 + g;
                af[mt][0] = s->act[r][ka + tig];
                af[mt][1] = s->act[r + 8][ka + tig];
                af[mt][2] = s->act[r][ka + tig + 4];
                af[mt][3] = s->act[r + 8][ka + tig + 4];
            }
#pragma unroll
            for (int j = 0; j < 4; j++) {
                int nn = wn * 32 + j * 8 + g;
                bf[j][0] = s->bs[buf][kb + tig][nn];
                bf[j][1] = s->bs[buf][kb + tig + 4][nn];
            }
#pragma unroll
            for (int mt = 0; mt < 2; mt++)
#pragma unroll
                for (int j = 0; j < 4; j++) mma8(acc[mt][j], af[mt], bf[j]);
        }
        if (c < 3) {
            __syncthreads();
            const int nb = (c + 1) & 1;
#pragma unroll
            for (int h = 0; h < 2; h++) {
                int rw = kw + 16 * h;
                s->bs[nb][rw][cw + 0] = f2tf(p[h][0].x); s->bs[nb][rw][cw + 1] = f2tf(p[h][0].y);
                s->bs[nb][rw][cw + 2] = f2tf(p[h][0].z); s->bs[nb][rw][cw + 3] = f2tf(p[h][0].w);
                s->bs[nb][rw][cw + 4] = f2tf(p[h][1].x); s->bs[nb][rw][cw + 5] = f2tf(p[h][1].y);
                s->bs[nb][rw][cw + 6] = f2tf(p[h][1].z); s->bs[nb][rw][cw + 7] = f2tf(p[h][1].w);
            }
            __syncthreads();
        }
    }
}

// ---- bias + layernorm + mish on acc, write result (tf32) back into act ----
__device__ __forceinline__ void ln_mish_act(SmemQ* s, float acc[2][4][4],
    const float* __restrict__ bias, const float* __restrict__ gam, const float* __restrict__ bet,
    int wm, int wn, int g, int tig)
{
    float2 bv[4], gv[4], bb[4];
#pragma unroll
    for (int j = 0; j < 4; j++) {
        int cc = wn * 32 + j * 8 + 2 * tig;
        bv[j] = *(const float2*)(bias + cc);
        gv[j] = *(const float2*)(gam + cc);
        bb[j] = *(const float2*)(bet + cc);
    }
#pragma unroll
    for (int mt = 0; mt < 2; mt++) {
        float s0 = 0.f, q0 = 0.f, s1 = 0.f, q1 = 0.f;
#pragma unroll
        for (int j = 0; j < 4; j++) {
            float a0 = acc[mt][j][0] + bv[j].x, a1 = acc[mt][j][1] + bv[j].y;
            float a2 = acc[mt][j][2] + bv[j].x, a3 = acc[mt][j][3] + bv[j].y;
            acc[mt][j][0] = a0; acc[mt][j][1] = a1; acc[mt][j][2] = a2; acc[mt][j][3] = a3;
            s0 += a0 + a1; q0 += a0 * a0 + a1 * a1;
            s1 += a2 + a3; q1 += a2 * a2 + a3 * a3;
        }
#pragma unroll
        for (int o = 1; o <= 2; o <<= 1) {
            s0 += __shfl_xor_sync(0xffffffffu, s0, o);
            q0 += __shfl_xor_sync(0xffffffffu, q0, o);
            s1 += __shfl_xor_sync(0xffffffffu, s1, o);
            q1 += __shfl_xor_sync(0xffffffffu, q1, o);
        }
        if (tig == 0) {
            int r = wm * 32 + mt * 16 + g;
            s->ssum[r][wn] = s0; s->ssq[r][wn] = q0;
            s->ssum[r + 8][wn] = s1; s->ssq[r + 8][wn] = q1;
        }
    }
    __syncthreads();   // partials ready; all warps done reading act
#pragma unroll
    for (int mt = 0; mt < 2; mt++) {
        int r0 = wm * 32 + mt * 16 + g, r1 = r0 + 8;
        float su0 = s->ssum[r0][0] + s->ssum[r0][1] + s->ssum[r0][2] + s->ssum[r0][3];
        float sq0 = s->ssq [r0][0] + s->ssq [r0][1] + s->ssq [r0][2] + s->ssq [r0][3];
        float mean0 = su0 * (1.f / 128.f);
        float var0  = sq0 * (1.f / 128.f) - mean0 * mean0;
        float rs0   = rsqrtf(var0 + 1e-5f);
        float su1 = s->ssum[r1][0] + s->ssum[r1][1] + s->ssum[r1][2] + s->ssum[r1][3];
        float sq1 = s->ssq [r1][0] + s->ssq [r1][1] + s->ssq [r1][2] + s->ssq [r1][3];
        float mean1 = su1 * (1.f / 128.f);
        float var1  = sq1 * (1.f / 128.f) - mean1 * mean1;
        float rs1   = rsqrtf(var1 + 1e-5f);
#pragma unroll
        for (int j = 0; j < 4; j++) {
            int cc = wn * 32 + j * 8 + 2 * tig;
            float o0 = mish_f((acc[mt][j][0] - mean0) * rs0 * gv[j].x + bb[j].x);
            float o1 = mish_f((acc[mt][j][1] - mean0) * rs0 * gv[j].y + bb[j].y);
            float o2 = mish_f((acc[mt][j][2] - mean1) * rs1 * gv[j].x + bb[j].x);
            float o3 = mish_f((acc[mt][j][3] - mean1) * rs1 * gv[j].y + bb[j].y);
            s->act[r0][cc] = f2tf(o0); s->act[r0][cc + 1] = f2tf(o1);
            s->act[r1][cc] = f2tf(o2); s->act[r1][cc + 1] = f2tf(o3);
        }
    }
    __syncthreads();
}

// ---- mapping: out = A @ W + bias (fp32 to gmem) ----
__global__ void __launch_bounds__(256, 2) map_kernel(
    const float* __restrict__ A, const float* __restrict__ W,
    const float* __restrict__ bias, float* __restrict__ out, int n)
{
    extern __shared__ char raw[];
    SmemQ* s = (SmemQ*)raw;
    const int tid = threadIdx.x, lane = tid & 31, warp = tid >> 5;
    const int wm = warp >> 2, wn = warp & 3, g = lane >> 2, tig = lane & 3;
    const int row0 = blockIdx.x * BR;

    fill_act(s, A, row0, n, tid);
    float acc[2][4][4];
    gemm_act_W(s, W, acc, wm, wn, g, tig, tid);

    float2 bv[4];
#pragma unroll
    for (int j = 0; j < 4; j++) bv[j] = *(const float2*)(bias + wn * 32 + j * 8 + 2 * tig);
#pragma unroll
    for (int mt = 0; mt < 2; mt++) {
        int gr0 = row0 + wm * 32 + mt * 16 + g, gr1 = gr0 + 8;
#pragma unroll
        for (int j = 0; j < 4; j++) {
            int cc = wn * 32 + j * 8 + 2 * tig;
            if (gr0 < n)
                *(float2*)(out + (size_t)gr0 * 128 + cc) =
                    make_float2(acc[mt][j][0] + bv[j].x, acc[mt][j][1] + bv[j].y);
            if (gr1 < n)
                *(float2*)(out + (size_t)gr1 * 128 + cc) =
                    make_float2(acc[mt][j][2] + bv[j].x, acc[mt][j][3] + bv[j].y);
        }
    }
}

// ---- fused: segsum( mlp2(A1; a-params) * mlp2(A2; b-params) ) += out ----
__global__ void __launch_bounds__(256, 2) quad_kernel(
    const float* __restrict__ A1, const float* __restrict__ A2,
    const float* __restrict__ W1a, const float* __restrict__ b1a,
    const float* __restrict__ g1a, const float* __restrict__ n1a,
    const float* __restrict__ W2a, const float* __restrict__ b2a,
    const float* __restrict__ W1b, const float* __restrict__ b1b,
    const float* __restrict__ g1b, const float* __restrict__ n1b,
    const float* __restrict__ W2b, const float* __restrict__ b2b,
    const int* __restrict__ batch, float* __restrict__ out, int n)
{
    extern __shared__ char raw[];
    SmemQ* s = (SmemQ*)raw;
    const int tid = threadIdx.x, lane = tid & 31, warp = tid >> 5;
    const int wm = warp >> 2, wn = warp & 3, g = lane >> 2, tig = lane & 3;
    const int row0 = blockIdx.x * BR;

    if (tid < BR) s->sbatch[tid] = (row0 + tid < n) ? batch[row0 + tid] : -1;
    fill_act(s, A1, row0, n, tid);

    float acc[2][4][4];
    // val side: h1v = LN/mish(A1@W1a + b1a); v = h1v@W2a + b2a (in regs)
    gemm_act_W(s, W1a, acc, wm, wn, g, tig, tid);
    ln_mish_act(s, acc, b1a, g1a, n1a, wm, wn, g, tig);
    gemm_act_W(s, W2a, acc, wm, wn, g, tig, tid);

    float vv[2][4][4];
    {
        float2 b2[4];
#pragma unroll
        for (int j = 0; j < 4; j++) b2[j] = *(const float2*)(b2a + wn * 32 + j * 8 + 2 * tig);
#pragma unroll
        for (int mt = 0; mt < 2; mt++)
#pragma unroll
            for (int j = 0; j < 4; j++) {
                vv[mt][j][0] = acc[mt][j][0] + b2[j].x;
                vv[mt][j][1] = acc[mt][j][1] + b2[j].y;
                vv[mt][j][2] = acc[mt][j][2] + b2[j].x;
                vv[mt][j][3] = acc[mt][j][3] + b2[j].y;
            }
    }
    __syncthreads();                 // all warps done reading act (h1v)

    // key side: kq = mlp2(A2); y = kq * v
    fill_act(s, A2, row0, n, tid);
    gemm_act_W(s, W1b, acc, wm, wn, g, tig, tid);
    ln_mish_act(s, acc, b1b, g1b, n1b, wm, wn, g, tig);
    gemm_act_W(s, W2b, acc, wm, wn, g, tig, tid);
    __syncthreads();                 // all warps done reading act (h1k)

    {
        float2 b2[4];
#pragma unroll
        for (int j = 0; j < 4; j++) b2[j] = *(const float2*)(b2b + wn * 32 + j * 8 + 2 * tig);
        float* Y = (float*)s->act;
#pragma unroll
        for (int mt = 0; mt < 2; mt++) {
            int r0 = wm * 32 + mt * 16 + g, r1 = r0 + 8;
#pragma unroll
            for (int j = 0; j < 4; j++) {
                int cc = wn * 32 + j * 8 + 2 * tig;
                Y[r0 * 132 + cc]     = (acc[mt][j][0] + b2[j].x) * vv[mt][j][0];
                Y[r0 * 132 + cc + 1] = (acc[mt][j][1] + b2[j].y) * vv[mt][j][1];
                Y[r1 * 132 + cc]     = (acc[mt][j][2] + b2[j].x) * vv[mt][j][2];
                Y[r1 * 132 + cc + 1] = (acc[mt][j][3] + b2[j].y) * vv[mt][j][3];
            }
        }
    }
    __syncthreads();

    // per-block run-length segment reduction + atomicAdd (2 x 32-row strips)
    {
        const float* Y = (const float*)s->act;
        int c = tid & 127, qq = tid >> 7;   // qq in 0..1
        int r = qq * 32;
        float a = 0.f;
        int cur = s->sbatch[r];
#pragma unroll 4
        for (int i = 0; i < 32; i++, r++) {
            int sbv = s->sbatch[r];
            if (sbv != cur) {
                if (cur >= 0) atomicAdd(out + (size_t)cur * 128 + c, a);
                a = 0.f; cur = sbv;
            }
            a += Y[r * 132 + c];
        }
        if (cur >= 0) atomicAdd(out + (size_t)cur * 128 + c, a);
    }
}

extern "C" void kernel_launch(void* const* d_in, const int* in_sizes, int n_in,
                              void* d_out, int out_size)
{
    const float* x     = (const float*)d_in[0];
    const int*   batch = (const int*)  d_in[1];
    const float* W_map = (const float*)d_in[3];
    const float* b_map = (const float*)d_in[4];
    const float* kW1 = (const float*)d_in[5],  *kb1 = (const float*)d_in[6];
    const float* kg  = (const float*)d_in[7],  *kbn = (const float*)d_in[8];
    const float* kW2 = (const float*)d_in[9],  *kb2 = (const float*)d_in[10];
    const float* vW1 = (const float*)d_in[11], *vb1 = (const float*)d_in[12];
    const float* vg  = (const float*)d_in[13], *vbn = (const float*)d_in[14];
    const float* vW2 = (const float*)d_in[15], *vb2 = (const float*)d_in[16];
    const float* iW_map = (const float*)d_in[17], *ib_map = (const float*)d_in[18];
    const float* ikW1 = (const float*)d_in[19], *ikb1 = (const float*)d_in[20];
    const float* ikg  = (const float*)d_in[21], *ikbn = (const float*)d_in[22];
    const float* ikW2 = (const float*)d_in[23], *ikb2 = (const float*)d_in[24];
    const float* ivW1 = (const float*)d_in[25], *ivb1 = (const float*)d_in[26];
    const float* ivg  = (const float*)d_in[27], *ivbn = (const float*)d_in[28];
    const float* ivW2 = (const float*)d_in[29], *ivb2 = (const float*)d_in[30];

    int n = in_sizes[0] / 128;
    float* out = (float*)d_out;

    float *keys, *k2; int* segstart;
    cudaGetSymbolAddress((void**)&keys, g_keys);
    cudaGetSymbolAddress((void**)&k2,   g_k2);
    cudaGetSymbolAddress((void**)&segstart, g_segstart);

    const int SMB = (int)sizeof(SmemQ);
    cudaFuncSetAttribute(map_kernel,  cudaFuncAttributeMaxDynamicSharedMemorySize, SMB);
    cudaFuncSetAttribute(quad_kernel, cudaFuncAttributeMaxDynamicSharedMemorySize, SMB);

    cudaMemsetAsync(d_out, 0, (size_t)out_size * sizeof(float));
    segstart_kernel<<<(NBATCH + 256) / 256, 256>>>(batch, n, segstart);

    int mb = (n + BR - 1) / BR;

    // outer encoder
    map_kernel<<<mb, 256, SMB>>>(x, W_map, b_map, keys, n);
    seg_softmax_kernel<<<NBATCH, 128>>>(keys, segstart);
    quad_kernel<<<mb, 256, SMB>>>(x, keys,
                                  vW1, vb1, vg, vbn, vW2, vb2,
                                  kW1, kb1, kg, kbn, kW2, kb2,
                                  batch, out, n);

    // inner encoder on keys
    map_kernel<<<mb, 256, SMB>>>(keys, iW_map, ib_map, k2, n);
    seg_softmax_kernel<<<NBATCH, 128>>>(k2, segstart);
    quad_kernel<<<mb, 256, SMB>>>(keys, k2,
                                  ivW1, ivb1, ivg, ivbn, ivW2, ivb2,
                                  ikW1, ikb1, ikg, ikbn, ikW2, ikb2,
                                  batch, out + (size_t)NBATCH * 128, n);
}

// round 13
// speedup vs baseline: 1.9312x; 1.4255x over previous
#include <cuda_runtime.h>
#include <math.h>
#include <stdint.h>

#define MAXN   500000
#define NBATCH 4096
#define AW     68                 // row stride in 32-bit words (half2-packed rows of 128 halves)
#define TILE_W (128 * AW)          // 8704 words = 34816 B per 128x128 half tile
#define TILE_C (TILE_W / 4)        // 2176 16-byte chunks

// ---- static scratch ----
__device__ __align__(16) float    g_keys[(size_t)MAXN * 128];
__device__ __align__(16) float    g_k2  [(size_t)MAXN * 128];
__device__ __align__(16) uint32_t g_wprep[10 * TILE_W];   // half2-packed [n][k], stride AW
__device__ int g_segstart[NBATCH + 1];

struct SmemH {                     // quad: 178688 B
    uint32_t act[TILE_W];          // activations, half2-packed [r][k]
    uint32_t w[4][TILE_W];         // 4 resident weight tiles; w[0..1] reused as Y (float, stride 132)
    float    ssum[128][4];
    float    ssq [128][4];
    int      sbatch[128];
};
struct SmemM {                     // map: 69632 B
    uint32_t act[TILE_W];
    uint32_t w[TILE_W];
};

__device__ __forceinline__ float mish_f(float x) {
    float sp = (x > 20.f) ? x : log1pf(__expf(x));
    return x * tanhf(sp);
}
__device__ __forceinline__ uint32_t pack_h2(float lo, float hi) {
    uint32_t r;
    asm("cvt.rn.f16x2.f32 %0, %1, %2;" : "=r"(r) : "f"(hi), "f"(lo));
    return r;
}
__device__ __forceinline__ uint32_t smem_u32(const void* p) {
    uint32_t a;
    asm("{ .reg .u64 t; cvta.to.shared.u64 t, %1; cvt.u32.u64 %0, t; }" : "=r"(a) : "l"(p));
    return a;
}
__device__ __forceinline__ void mma16(float c[4], uint32_t a0, uint32_t a1, uint32_t a2,
                                      uint32_t a3, uint32_t b0, uint32_t b1) {
    asm volatile("mma.sync.aligned.m16n8k16.row.col.f32.f16.f16.f32 "
        "{%0,%1,%2,%3},{%4,%5,%6,%7},{%8,%9},{%0,%1,%2,%3};"
        : "+f"(c[0]), "+f"(c[1]), "+f"(c[2]), "+f"(c[3])
        : "r"(a0), "r"(a1), "r"(a2), "r"(a3), "r"(b0), "r"(b1));
}

// ---- segment starts via binary search over sorted batch ----
__global__ void segstart_kernel(const int* __restrict__ batch, int n, int* __restrict__ segstart) {
    int b = blockIdx.x * blockDim.x + threadIdx.x;
    if (b > NBATCH) return;
    int lo = 0, hi = n;
    while (lo < hi) { int m = (lo + hi) >> 1; if (batch[m] < b) lo = m + 1; else hi = m; }
    segstart[b] = lo;
}

// ---- weight prep: W[k][n] fp32 -> g_wprep[wi]: [n][k] half2-packed, row stride AW words ----
__global__ void prep_all(const float* w0, const float* w1, const float* w2, const float* w3,
                         const float* w4, const float* w5, const float* w6, const float* w7,
                         const float* w8, const float* w9) {
    const float* srcs[10] = {w0, w1, w2, w3, w4, w5, w6, w7, w8, w9};
    int wi = blockIdx.y;
    const float* W = srcs[wi];
    int e = blockIdx.x * 256 + threadIdx.x;       // grid.x = 32 -> 8192 = 128 n * 64 words
    int nn = e >> 6, wk = e & 63;
    int k = wk * 2;
    g_wprep[wi * TILE_W + nn * AW + wk] = pack_h2(W[k * 128 + nn], W[(k + 1) * 128 + nn]);
}

// ---- per-segment, per-feature softmax, online, in place ----
__global__ void __launch_bounds__(128) seg_softmax_kernel(
    float* __restrict__ io, const int* __restrict__ segstart)
{
    int b = blockIdx.x;
    int s0 = segstart[b], e = segstart[b + 1];
    int t = threadIdx.x;
    if (s0 >= e) return;
    float m = -3.4e38f, d = 0.f;
    for (int r = s0; r < e; r++) {
        float v = io[(size_t)r * 128 + t];
        float nm = fmaxf(m, v);
        d = d * __expf(m - nm) + __expf(v - nm);
        m = nm;
    }
    float inv = 1.f / d;
    for (int r = s0; r < e; r++) {
        float v = io[(size_t)r * 128 + t];
        io[(size_t)r * 128 + t] = __expf(v - m) * inv;
    }
}

// ---- cp.async prefetch of one prepped tile into smem ----
__device__ __forceinline__ void fetch_tile(uint32_t dst, const uint32_t* __restrict__ src, int tid) {
#pragma unroll
    for (int i = 0; i < 5; i++) {
        int idx = tid + i * 512;
        if (idx < TILE_C)
            asm volatile("cp.async.cg.shared.global [%0], [%1], 16;"
                         :: "r"(dst + idx * 16), "l"(src + idx * 4) : "memory");
    }
}
#define CP_COMMIT() asm volatile("cp.async.commit_group;" ::: "memory")
#define CP_WAIT0()  asm volatile("cp.async.wait_group 0;" ::: "memory")

// ---- load 128x128 fp32 tile -> smem act (half2-packed), zero-padded. 512 threads ----
__device__ __forceinline__ void fill_act(uint32_t* __restrict__ act, const float* __restrict__ src,
                                         int row0, int n, int tid) {
#pragma unroll
    for (int i = 0; i < 8; i++) {
        int e = tid + i * 512;                    // 0..4095
        int r = e >> 5, c4 = (e & 31) * 4;
        int gr = row0 + r;
        float4 v = make_float4(0.f, 0.f, 0.f, 0.f);
        if (gr < n) v = *(const float4*)(src + (size_t)gr * 128 + c4);
        uint2 st;
        st.x = pack_h2(v.x, v.y);
        st.y = pack_h2(v.z, v.w);
        *(uint2*)&act[r * AW + (e & 31) * 2] = st;
    }
}

// ---- GEMM core: acc[128x128] = act @ W, both smem-resident fp16. No internal syncs. ----
// 16 warps, warp tile 32x32: rows wm*32+mt*16+g(+8), cols wn*32+j*8+2tig(+1)
__device__ __forceinline__ void gemm_h(const uint32_t* __restrict__ act,
                                       const uint32_t* __restrict__ w,
                                       float acc[2][4][4],
                                       int wm, int wn, int g, int tig) {
    const uint32_t* A = act + (wm * 32 + g) * AW + tig;
    const uint32_t* B = w + (wn * 32 + g) * AW + tig;
#pragma unroll
    for (int mt = 0; mt < 2; mt++)
#pragma unroll
        for (int j = 0; j < 4; j++)
#pragma unroll
            for (int c = 0; c < 4; c++) acc[mt][j][c] = 0.f;

#pragma unroll
    for (int ks = 0; ks < 8; ks++) {
        const int ko = ks * 8;
        uint32_t a00 = A[ko],           a01 = A[8 * AW + ko];
        uint32_t a02 = A[ko + 4],       a03 = A[8 * AW + ko + 4];
        uint32_t a10 = A[16 * AW + ko], a11 = A[24 * AW + ko];
        uint32_t a12 = A[16 * AW + ko + 4], a13 = A[24 * AW + ko + 4];
        uint32_t b00 = B[ko],           b01 = B[ko + 4];
        uint32_t b10 = B[8 * AW + ko],  b11 = B[8 * AW + ko + 4];
        uint32_t b20 = B[16 * AW + ko], b21 = B[16 * AW + ko + 4];
        uint32_t b30 = B[24 * AW + ko], b31 = B[24 * AW + ko + 4];
        mma16(acc[0][0], a00, a01, a02, a03, b00, b01);
        mma16(acc[0][1], a00, a01, a02, a03, b10, b11);
        mma16(acc[0][2], a00, a01, a02, a03, b20, b21);
        mma16(acc[0][3], a00, a01, a02, a03, b30, b31);
        mma16(acc[1][0], a10, a11, a12, a13, b00, b01);
        mma16(acc[1][1], a10, a11, a12, a13, b10, b11);
        mma16(acc[1][2], a10, a11, a12, a13, b20, b21);
        mma16(acc[1][3], a10, a11, a12, a13, b30, b31);
    }
}

// ---- bias + layernorm + mish on acc; write result (half2) back into act ----
__device__ __forceinline__ void ln_mish_act(SmemH* s, float acc[2][4][4],
    const float* __restrict__ bias, const float* __restrict__ gam, const float* __restrict__ bet,
    int wm, int wn, int g, int tig)
{
    float2 bv[4], gv[4], bb[4];
#pragma unroll
    for (int j = 0; j < 4; j++) {
        int cc = wn * 32 + j * 8 + 2 * tig;
        bv[j] = *(const float2*)(bias + cc);
        gv[j] = *(const float2*)(gam + cc);
        bb[j] = *(const float2*)(bet + cc);
    }
#pragma unroll
    for (int mt = 0; mt < 2; mt++) {
        float s0 = 0.f, q0 = 0.f, s1 = 0.f, q1 = 0.f;
#pragma unroll
        for (int j = 0; j < 4; j++) {
            float a0 = acc[mt][j][0] + bv[j].x, a1 = acc[mt][j][1] + bv[j].y;
            float a2 = acc[mt][j][2] + bv[j].x, a3 = acc[mt][j][3] + bv[j].y;
            acc[mt][j][0] = a0; acc[mt][j][1] = a1; acc[mt][j][2] = a2; acc[mt][j][3] = a3;
            s0 += a0 + a1; q0 += a0 * a0 + a1 * a1;
            s1 += a2 + a3; q1 += a2 * a2 + a3 * a3;
        }
#pragma unroll
        for (int o = 1; o <= 2; o <<= 1) {
            s0 += __shfl_xor_sync(0xffffffffu, s0, o);
            q0 += __shfl_xor_sync(0xffffffffu, q0, o);
            s1 += __shfl_xor_sync(0xffffffffu, s1, o);
            q1 += __shfl_xor_sync(0xffffffffu, q1, o);
        }
        if (tig == 0) {
            int r = wm * 32 + mt * 16 + g;
            s->ssum[r][wn] = s0; s->ssq[r][wn] = q0;
            s->ssum[r + 8][wn] = s1; s->ssq[r + 8][wn] = q1;
        }
    }
    __syncthreads();   // partials ready; all warps done reading act
#pragma unroll
    for (int mt = 0; mt < 2; mt++) {
        int r0 = wm * 32 + mt * 16 + g, r1 = r0 + 8;
        float su0 = s->ssum[r0][0] + s->ssum[r0][1] + s->ssum[r0][2] + s->ssum[r0][3];
        float sq0 = s->ssq [r0][0] + s->ssq [r0][1] + s->ssq [r0][2] + s->ssq [r0][3];
        float mean0 = su0 * (1.f / 128.f);
        float var0  = sq0 * (1.f / 128.f) - mean0 * mean0;
        float rs0   = rsqrtf(var0 + 1e-5f);
        float su1 = s->ssum[r1][0] + s->ssum[r1][1] + s->ssum[r1][2] + s->ssum[r1][3];
        float sq1 = s->ssq [r1][0] + s->ssq [r1][1] + s->ssq [r1][2] + s->ssq [r1][3];
        float mean1 = su1 * (1.f / 128.f);
        float var1  = sq1 * (1.f / 128.f) - mean1 * mean1;
        float rs1   = rsqrtf(var1 + 1e-5f);
#pragma unroll
        for (int j = 0; j < 4; j++) {
            int wd = wn * 16 + j * 4 + tig;       // word index of cols (2tig, 2tig+1) in 8-group
            float o0 = mish_f((acc[mt][j][0] - mean0) * rs0 * gv[j].x + bb[j].x);
            float o1 = mish_f((acc[mt][j][1] - mean0) * rs0 * gv[j].y + bb[j].y);
            float o2 = mish_f((acc[mt][j][2] - mean1) * rs1 * gv[j].x + bb[j].x);
            float o3 = mish_f((acc[mt][j][3] - mean1) * rs1 * gv[j].y + bb[j].y);
            s->act[r0 * AW + wd] = pack_h2(o0, o1);
            s->act[r1 * AW + wd] = pack_h2(o2, o3);
        }
    }
    __syncthreads();
}

// ---- mapping: out = A @ W + bias (fp32 to gmem) ----
__global__ void __launch_bounds__(512, 1) map_kernel(
    const float* __restrict__ A, const uint32_t* __restrict__ Wp,
    const float* __restrict__ bias, float* __restrict__ out, int n)
{
    extern __shared__ char raw[];
    SmemM* s = (SmemM*)raw;
    const int tid = threadIdx.x, lane = tid & 31, warp = tid >> 5;
    const int wm = warp >> 2, wn = warp & 3, g = lane >> 2, tig = lane & 3;
    const int row0 = blockIdx.x * 128;

    fetch_tile(smem_u32(s->w), Wp, tid);
    CP_COMMIT();
    fill_act(s->act, A, row0, n, tid);
    CP_WAIT0();
    __syncthreads();

    float acc[2][4][4];
    gemm_h(s->act, s->w, acc, wm, wn, g, tig);

    float2 bv[4];
#pragma unroll
    for (int j = 0; j < 4; j++) bv[j] = *(const float2*)(bias + wn * 32 + j * 8 + 2 * tig);
#pragma unroll
    for (int mt = 0; mt < 2; mt++) {
        int gr0 = row0 + wm * 32 + mt * 16 + g, gr1 = gr0 + 8;
#pragma unroll
        for (int j = 0; j < 4; j++) {
            int cc = wn * 32 + j * 8 + 2 * tig;
            if (gr0 < n)
                *(float2*)(out + (size_t)gr0 * 128 + cc) =
                    make_float2(acc[mt][j][0] + bv[j].x, acc[mt][j][1] + bv[j].y);
            if (gr1 < n)
                *(float2*)(out + (size_t)gr1 * 128 + cc) =
                    make_float2(acc[mt][j][2] + bv[j].x, acc[mt][j][3] + bv[j].y);
        }
    }
}

// ---- fused: segsum( mlp2(A1; a-params) * mlp2(A2; b-params) ) += out ----
__global__ void __launch_bounds__(512, 1) quad_kernel(
    const float* __restrict__ A1, const float* __restrict__ A2,
    const uint32_t* __restrict__ W1a, const float* __restrict__ b1a,
    const float* __restrict__ g1a, const float* __restrict__ n1a,
    const uint32_t* __restrict__ W2a, const float* __restrict__ b2a,
    const uint32_t* __restrict__ W1b, const float* __restrict__ b1b,
    const float* __restrict__ g1b, const float* __restrict__ n1b,
    const uint32_t* __restrict__ W2b, const float* __restrict__ b2b,
    const int* __restrict__ batch, float* __restrict__ out, int n)
{
    extern __shared__ char raw[];
    SmemH* s = (SmemH*)raw;
    const int tid = threadIdx.x, lane = tid & 31, warp = tid >> 5;
    const int wm = warp >> 2, wn = warp & 3, g = lane >> 2, tig = lane & 3;
    const int row0 = blockIdx.x * 128;

    // prefetch all four weight tiles; fill act meanwhile
    fetch_tile(smem_u32(s->w[0]), W1a, tid);
    fetch_tile(smem_u32(s->w[1]), W2a, tid);
    fetch_tile(smem_u32(s->w[2]), W1b, tid);
    fetch_tile(smem_u32(s->w[3]), W2b, tid);
    CP_COMMIT();
    if (tid < 128) s->sbatch[tid] = (row0 + tid < n) ? batch[row0 + tid] : -1;
    fill_act(s->act, A1, row0, n, tid);
    CP_WAIT0();
    __syncthreads();

    float acc[2][4][4];
    // val side: h1v = LN/mish(A1@W1a + b1a); v = h1v@W2a + b2a (in regs)
    gemm_h(s->act, s->w[0], acc, wm, wn, g, tig);
    ln_mish_act(s, acc, b1a, g1a, n1a, wm, wn, g, tig);
    gemm_h(s->act, s->w[1], acc, wm, wn, g, tig);

    float vv[2][4][4];
    {
        float2 b2[4];
#pragma unroll
        for (int j = 0; j < 4; j++) b2[j] = *(const float2*)(b2a + wn * 32 + j * 8 + 2 * tig);
#pragma unroll
        for (int mt = 0; mt < 2; mt++)
#pragma unroll
            for (int j = 0; j < 4; j++) {
                vv[mt][j][0] = acc[mt][j][0] + b2[j].x;
                vv[mt][j][1] = acc[mt][j][1] + b2[j].y;
                vv[mt][j][2] = acc[mt][j][2] + b2[j].x;
                vv[mt][j][3] = acc[mt][j][3] + b2[j].y;
            }
    }
    __syncthreads();                 // all warps done reading act (h1v)

    // key side: kq = mlp2(A2); y = kq * v
    fill_act(s->act, A2, row0, n, tid);
    __syncthreads();
    gemm_h(s->act, s->w[2], acc, wm, wn, g, tig);
    ln_mish_act(s, acc, b1b, g1b, n1b, wm, wn, g, tig);
    gemm_h(s->act, s->w[3], acc, wm, wn, g, tig);
    __syncthreads();                 // all warps done reading act (h1k) and w[0..1]

    // y = (kq + b2b) * vv -> Y overlaying w[0..1] (float, stride 132)
    float* Y = (float*)s->w[0];
    {
        float2 b2[4];
#pragma unroll
        for (int j = 0; j < 4; j++) b2[j] = *(const float2*)(b2b + wn * 32 + j * 8 + 2 * tig);
#pragma unroll
        for (int mt = 0; mt < 2; mt++) {
            int r0 = wm * 32 + mt * 16 + g, r1 = r0 + 8;
#pragma unroll
            for (int j = 0; j < 4; j++) {
                int cc = wn * 32 + j * 8 + 2 * tig;
                *(float2*)&Y[r0 * 132 + cc] = make_float2(
                    (acc[mt][j][0] + b2[j].x) * vv[mt][j][0],
                    (acc[mt][j][1] + b2[j].y) * vv[mt][j][1]);
                *(float2*)&Y[r1 * 132 + cc] = make_float2(
                    (acc[mt][j][2] + b2[j].x) * vv[mt][j][2],
                    (acc[mt][j][3] + b2[j].y) * vv[mt][j][3]);
            }
        }
    }
    __syncthreads();

    // per-block run-length segment reduction + atomicAdd (4 x 32-row strips)
    {
        int c = tid & 127, qq = tid >> 7;
        int r = qq * 32;
        float a = 0.f;
        int cur = s->sbatch[r];
#pragma unroll 4
        for (int i = 0; i < 32; i++, r++) {
            int sbv = s->sbatch[r];
            if (sbv != cur) {
                if (cur >= 0) atomicAdd(out + (size_t)cur * 128 + c, a);
                a = 0.f; cur = sbv;
            }
            a += Y[r * 132 + c];
        }
        if (cur >= 0) atomicAdd(out + (size_t)cur * 128 + c, a);
    }
}

extern "C" void kernel_launch(void* const* d_in, const int* in_sizes, int n_in,
                              void* d_out, int out_size)
{
    const float* x     = (const float*)d_in[0];
    const int*   batch = (const int*)  d_in[1];
    const float* W_map = (const float*)d_in[3];
    const float* b_map = (const float*)d_in[4];
    const float* kW1 = (const float*)d_in[5],  *kb1 = (const float*)d_in[6];
    const float* kg  = (const float*)d_in[7],  *kbn = (const float*)d_in[8];
    const float* kW2 = (const float*)d_in[9],  *kb2 = (const float*)d_in[10];
    const float* vW1 = (const float*)d_in[11], *vb1 = (const float*)d_in[12];
    const float* vg  = (const float*)d_in[13], *vbn = (const float*)d_in[14];
    const float* vW2 = (const float*)d_in[15], *vb2 = (const float*)d_in[16];
    const float* iW_map = (const float*)d_in[17], *ib_map = (const float*)d_in[18];
    const float* ikW1 = (const float*)d_in[19], *ikb1 = (const float*)d_in[20];
    const float* ikg  = (const float*)d_in[21], *ikbn = (const float*)d_in[22];
    const float* ikW2 = (const float*)d_in[23], *ikb2 = (const float*)d_in[24];
    const float* ivW1 = (const float*)d_in[25], *ivb1 = (const float*)d_in[26];
    const float* ivg  = (const float*)d_in[27], *ivbn = (const float*)d_in[28];
    const float* ivW2 = (const float*)d_in[29], *ivb2 = (const float*)d_in[30];

    int n = in_sizes[0] / 128;
    float* out = (float*)d_out;

    float *keys, *k2; int* segstart; uint32_t* wprep;
    cudaGetSymbolAddress((void**)&keys, g_keys);
    cudaGetSymbolAddress((void**)&k2,   g_k2);
    cudaGetSymbolAddress((void**)&segstart, g_segstart);
    cudaGetSymbolAddress((void**)&wprep, g_wprep);

    cudaFuncSetAttribute(map_kernel,  cudaFuncAttributeMaxDynamicSharedMemorySize, (int)sizeof(SmemM));
    cudaFuncSetAttribute(quad_kernel, cudaFuncAttributeMaxDynamicSharedMemorySize, (int)sizeof(SmemH));

    cudaMemsetAsync(d_out, 0, (size_t)out_size * sizeof(float));
    segstart_kernel<<<(NBATCH + 256) / 256, 256>>>(batch, n, segstart);
    // weight slots: 0=W_map 1=kW1 2=kW2 3=vW1 4=vW2 5=iW_map 6=ikW1 7=ikW2 8=ivW1 9=ivW2
    prep_all<<<dim3(32, 10), 256>>>(W_map, kW1, kW2, vW1, vW2, iW_map, ikW1, ikW2, ivW1, ivW2);

    int mb = (n + 127) / 128;
#define WSLOT(i) (wprep + (size_t)(i) * TILE_W)

    // outer encoder
    map_kernel<<<mb, 512, sizeof(SmemM)>>>(x, WSLOT(0), b_map, keys, n);
    seg_softmax_kernel<<<NBATCH, 128>>>(keys, segstart);
    quad_kernel<<<mb, 512, sizeof(SmemH)>>>(x, keys,
                                  WSLOT(3), vb1, vg, vbn, WSLOT(4), vb2,
                                  WSLOT(1), kb1, kg, kbn, WSLOT(2), kb2,
                                  batch, out, n);

    // inner encoder on keys
    map_kernel<<<mb, 512, sizeof(SmemM)>>>(keys, WSLOT(5), ib_map, k2, n);
    seg_softmax_kernel<<<NBATCH, 128>>>(k2, segstart);
    quad_kernel<<<mb, 512, sizeof(SmemH)>>>(keys, k2,
                                  WSLOT(8), ivb1, ivg, ivbn, WSLOT(9), ivb2,
                                  WSLOT(6), ikb1, ikg, ikbn, WSLOT(7), ikb2,
                                  batch, out + (size_t)NBATCH * 128, n);
}

// round 15
// speedup vs baseline: 2.0878x; 1.0811x over previous
#include <cuda_runtime.h>
#include <cuda_fp16.h>
#include <math.h>
#include <stdint.h>

#define MAXN   500000
#define NBATCH 4096
#define AW     68                 // smem row stride in 32-bit words (128 halves + pad)
#define TILE_W (128 * AW)
#define TILE_C (TILE_W / 4)

// ---- static scratch ----
__device__ __align__(16) float    g_key0 [(size_t)MAXN * 128];   // pre-softmax (fp32)
__device__ __align__(16) float    g_key0b[(size_t)MAXN * 128];   // inner pre-softmax (fp32)
__device__ __align__(16) uint32_t g_keysh[(size_t)MAXN * 64];    // softmaxed keys (half2)
__device__ __align__(16) uint32_t g_k2h  [(size_t)MAXN * 64];    // softmaxed inner keys (half2)
__device__ __align__(16) uint32_t g_wprep[10 * TILE_W];          // half2 [n][k], stride AW
__device__ int g_segstart[NBATCH + 1];

struct SmemH {                     // quad
    uint32_t act[TILE_W];
    uint32_t w[4][TILE_W];         // w[0..1] reused as Y (float, stride 132)
    float    ssum[128][4];
    float    ssq [128][4];
    int      sbatch[128];
};
struct SmemM {                     // map
    uint32_t act[TILE_W];
    uint32_t w[TILE_W];
};

__device__ __forceinline__ float mish_f(float x) {
    float sp = (x > 20.f) ? x : log1pf(__expf(x));
    return x * tanhf(sp);
}
__device__ __forceinline__ uint32_t pack_h2(float lo, float hi) {
    uint32_t r;
    asm("cvt.rn.f16x2.f32 %0, %1, %2;" : "=r"(r) : "f"(hi), "f"(lo));
    return r;
}
__device__ __forceinline__ uint32_t smem_u32(const void* p) {
    uint32_t a;
    asm("{ .reg .u64 t; cvta.to.shared.u64 t, %1; cvt.u32.u64 %0, t; }" : "=r"(a) : "l"(p));
    return a;
}
__device__ __forceinline__ void mma16(float c[4], uint32_t a0, uint32_t a1, uint32_t a2,
                                      uint32_t a3, uint32_t b0, uint32_t b1) {
    asm volatile("mma.sync.aligned.m16n8k16.row.col.f32.f16.f16.f32 "
        "{%0,%1,%2,%3},{%4,%5,%6,%7},{%8,%9},{%0,%1,%2,%3};"
        : "+f"(c[0]), "+f"(c[1]), "+f"(c[2]), "+f"(c[3])
        : "r"(a0), "r"(a1), "r"(a2), "r"(a3), "r"(b0), "r"(b1));
}

// ---- segment starts ----
__global__ void segstart_kernel(const int* __restrict__ batch, int n, int* __restrict__ segstart) {
    int b = blockIdx.x * blockDim.x + threadIdx.x;
    if (b > NBATCH) return;
    int lo = 0, hi = n;
    while (lo < hi) { int m = (lo + hi) >> 1; if (batch[m] < b) lo = m + 1; else hi = m; }
    segstart[b] = lo;
}

// ---- weight prep: W[k][n] fp32 -> half2 [n][k], stride AW ----
__global__ void prep_all(const float* w0, const float* w1, const float* w2, const float* w3,
                         const float* w4, const float* w5, const float* w6, const float* w7,
                         const float* w8, const float* w9) {
    const float* srcs[10] = {w0, w1, w2, w3, w4, w5, w6, w7, w8, w9};
    int wi = blockIdx.y;
    const float* W = srcs[wi];
    int e = blockIdx.x * 256 + threadIdx.x;       // 0..8191
    int nn = e >> 6, wk = e & 63;
    int k = wk * 2;
    g_wprep[wi * TILE_W + nn * AW + wk] = pack_h2(W[k * 128 + nn], W[(k + 1) * 128 + nn]);
}

// ---- softmax: fp32 in, fp16 out. pass1 4-way unrolled online; pass2 normalize ----
__global__ void __launch_bounds__(128) seg_softmax_h(
    const float* __restrict__ in, __half* __restrict__ outh,
    const int* __restrict__ segstart)
{
    int b = blockIdx.x;
    int s0 = segstart[b], e = segstart[b + 1];
    int t = threadIdx.x;
    if (s0 >= e) return;
    float m0 = -3.4e38f, m1 = -3.4e38f, m2 = -3.4e38f, m3 = -3.4e38f;
    float d0 = 0.f, d1 = 0.f, d2 = 0.f, d3 = 0.f;
    int r = s0;
    for (; r + 3 < e; r += 4) {
        float v0 = in[(size_t)(r + 0) * 128 + t];
        float v1 = in[(size_t)(r + 1) * 128 + t];
        float v2 = in[(size_t)(r + 2) * 128 + t];
        float v3 = in[(size_t)(r + 3) * 128 + t];
        float n0 = fmaxf(m0, v0); d0 = d0 * __expf(m0 - n0) + __expf(v0 - n0); m0 = n0;
        float n1 = fmaxf(m1, v1); d1 = d1 * __expf(m1 - n1) + __expf(v1 - n1); m1 = n1;
        float n2 = fmaxf(m2, v2); d2 = d2 * __expf(m2 - n2) + __expf(v2 - n2); m2 = n2;
        float n3 = fmaxf(m3, v3); d3 = d3 * __expf(m3 - n3) + __expf(v3 - n3); m3 = n3;
    }
    for (; r < e; r++) {
        float v = in[(size_t)r * 128 + t];
        float nm = fmaxf(m0, v); d0 = d0 * __expf(m0 - nm) + __expf(v - nm); m0 = nm;
    }
    float m = fmaxf(fmaxf(m0, m1), fmaxf(m2, m3));
    float d = d0 * __expf(m0 - m) + d1 * __expf(m1 - m)
            + d2 * __expf(m2 - m) + d3 * __expf(m3 - m);
    float inv = 1.f / d;
    for (r = s0; r < e; r++) {
        float v = in[(size_t)r * 128 + t];
        outh[(size_t)r * 128 + t] = __float2half_rn(__expf(v - m) * inv);
    }
}

// ---- cp.async prefetch of one prepped weight tile ----
__device__ __forceinline__ void fetch_tile(uint32_t dst, const uint32_t* __restrict__ src, int tid) {
#pragma unroll
    for (int i = 0; i < 5; i++) {
        int idx = tid + i * 512;
        if (idx < TILE_C)
            asm volatile("cp.async.cg.shared.global [%0], [%1], 16;"
                         :: "r"(dst + idx * 16), "l"(src + idx * 4) : "memory");
    }
}
#define CP_COMMIT() asm volatile("cp.async.commit_group;" ::: "memory")
#define CP_WAIT0()  asm volatile("cp.async.wait_group 0;" ::: "memory")

// ---- fill act from fp32 source (convert) ----
__device__ __forceinline__ void fill_act_f(uint32_t* __restrict__ act, const float* __restrict__ src,
                                           int row0, int n, int tid) {
#pragma unroll
    for (int i = 0; i < 8; i++) {
        int e = tid + i * 512;
        int r = e >> 5, c4 = (e & 31) * 4;
        int gr = row0 + r;
        float4 v = make_float4(0.f, 0.f, 0.f, 0.f);
        if (gr < n) v = *(const float4*)(src + (size_t)gr * 128 + c4);
        uint2 st;
        st.x = pack_h2(v.x, v.y);
        st.y = pack_h2(v.z, v.w);
        *(uint2*)&act[r * AW + (e & 31) * 2] = st;
    }
}

// ---- fill act from half source: raw cp.async copy (zero-fill past n) ----
__device__ __forceinline__ void fill_act_h(uint32_t act_addr, const uint32_t* __restrict__ srch,
                                           int row0, int n, int tid) {
#pragma unroll
    for (int i = 0; i < 4; i++) {
        int e = tid + i * 512;                    // 0..2047 = 128 rows x 16 chunks
        int r = e >> 4, c = e & 15;
        int gr = row0 + r;
        int sz = (gr < n) ? 16 : 0;
        size_t so = (size_t)(gr < n ? gr : 0) * 64 + c * 4;
        asm volatile("cp.async.cg.shared.global [%0], [%1], 16, %2;"
                     :: "r"(act_addr + (uint32_t)((r * AW + c * 4) * 4)),
                        "l"(srch + so), "r"(sz) : "memory");
    }
}

// ---- GEMM core: acc[128x128] = act @ W, both smem-resident fp16 ----
__device__ __forceinline__ void gemm_h(const uint32_t* __restrict__ act,
                                       const uint32_t* __restrict__ w,
                                       float acc[2][4][4],
                                       int wm, int wn, int g, int tig) {
    const uint32_t* A = act + (wm * 32 + g) * AW + tig;
    const uint32_t* B = w + (wn * 32 + g) * AW + tig;
#pragma unroll
    for (int mt = 0; mt < 2; mt++)
#pragma unroll
        for (int j = 0; j < 4; j++)
#pragma unroll
            for (int c = 0; c < 4; c++) acc[mt][j][c] = 0.f;

#pragma unroll
    for (int ks = 0; ks < 8; ks++) {
        const int ko = ks * 8;
        uint32_t a00 = A[ko],               a01 = A[8 * AW + ko];
        uint32_t a02 = A[ko + 4],           a03 = A[8 * AW + ko + 4];
        uint32_t a10 = A[16 * AW + ko],     a11 = A[24 * AW + ko];
        uint32_t a12 = A[16 * AW + ko + 4], a13 = A[24 * AW + ko + 4];
        uint32_t b00 = B[ko],               b01 = B[ko + 4];
        uint32_t b10 = B[8 * AW + ko],      b11 = B[8 * AW + ko + 4];
        uint32_t b20 = B[16 * AW + ko],     b21 = B[16 * AW + ko + 4];
        uint32_t b30 = B[24 * AW + ko],     b31 = B[24 * AW + ko + 4];
        mma16(acc[0][0], a00, a01, a02, a03, b00, b01);
        mma16(acc[0][1], a00, a01, a02, a03, b10, b11);
        mma16(acc[0][2], a00, a01, a02, a03, b20, b21);
        mma16(acc[0][3], a00, a01, a02, a03, b30, b31);
        mma16(acc[1][0], a10, a11, a12, a13, b00, b01);
        mma16(acc[1][1], a10, a11, a12, a13, b10, b11);
        mma16(acc[1][2], a10, a11, a12, a13, b20, b21);
        mma16(acc[1][3], a10, a11, a12, a13, b30, b31);
    }
}

// ---- bias + layernorm + mish; write result (half2) back into act ----
__device__ __forceinline__ void ln_mish_act(SmemH* s, float acc[2][4][4],
    const float* __restrict__ bias, const float* __restrict__ gam, const float* __restrict__ bet,
    int wm, int wn, int g, int tig)
{
    float2 bv[4], gv[4], bb[4];
#pragma unroll
    for (int j = 0; j < 4; j++) {
        int cc = wn * 32 + j * 8 + 2 * tig;
        bv[j] = *(const float2*)(bias + cc);
        gv[j] = *(const float2*)(gam + cc);
        bb[j] = *(const float2*)(bet + cc);
    }
#pragma unroll
    for (int mt = 0; mt < 2; mt++) {
        float s0 = 0.f, q0 = 0.f, s1 = 0.f, q1 = 0.f;
#pragma unroll
        for (int j = 0; j < 4; j++) {
            float a0 = acc[mt][j][0] + bv[j].x, a1 = acc[mt][j][1] + bv[j].y;
            float a2 = acc[mt][j][2] + bv[j].x, a3 = acc[mt][j][3] + bv[j].y;
            acc[mt][j][0] = a0; acc[mt][j][1] = a1; acc[mt][j][2] = a2; acc[mt][j][3] = a3;
            s0 += a0 + a1; q0 += a0 * a0 + a1 * a1;
            s1 += a2 + a3; q1 += a2 * a2 + a3 * a3;
        }
#pragma unroll
        for (int o = 1; o <= 2; o <<= 1) {
            s0 += __shfl_xor_sync(0xffffffffu, s0, o);
            q0 += __shfl_xor_sync(0xffffffffu, q0, o);
            s1 += __shfl_xor_sync(0xffffffffu, s1, o);
            q1 += __shfl_xor_sync(0xffffffffu, q1, o);
        }
        if (tig == 0) {
            int r = wm * 32 + mt * 16 + g;
            s->ssum[r][wn] = s0; s->ssq[r][wn] = q0;
            s->ssum[r + 8][wn] = s1; s->ssq[r + 8][wn] = q1;
        }
    }
    __syncthreads();
#pragma unroll
    for (int mt = 0; mt < 2; mt++) {
        int r0 = wm * 32 + mt * 16 + g, r1 = r0 + 8;
        float su0 = s->ssum[r0][0] + s->ssum[r0][1] + s->ssum[r0][2] + s->ssum[r0][3];
        float sq0 = s->ssq [r0][0] + s->ssq [r0][1] + s->ssq [r0][2] + s->ssq [r0][3];
        float mean0 = su0 * (1.f / 128.f);
        float var0  = sq0 * (1.f / 128.f) - mean0 * mean0;
        float rs0   = rsqrtf(var0 + 1e-5f);
        float su1 = s->ssum[r1][0] + s->ssum[r1][1] + s->ssum[r1][2] + s->ssum[r1][3];
        float sq1 = s->ssq [r1][0] + s->ssq [r1][1] + s->ssq [r1][2] + s->ssq [r1][3];
        float mean1 = su1 * (1.f / 128.f);
        float var1  = sq1 * (1.f / 128.f) - mean1 * mean1;
        float rs1   = rsqrtf(var1 + 1e-5f);
#pragma unroll
        for (int j = 0; j < 4; j++) {
            int wd = wn * 16 + j * 4 + tig;
            float o0 = mish_f((acc[mt][j][0] - mean0) * rs0 * gv[j].x + bb[j].x);
            float o1 = mish_f((acc[mt][j][1] - mean0) * rs0 * gv[j].y + bb[j].y);
            float o2 = mish_f((acc[mt][j][2] - mean1) * rs1 * gv[j].x + bb[j].x);
            float o3 = mish_f((acc[mt][j][3] - mean1) * rs1 * gv[j].y + bb[j].y);
            s->act[r0 * AW + wd] = pack_h2(o0, o1);
            s->act[r1 * AW + wd] = pack_h2(o2, o3);
        }
    }
    __syncthreads();
}

// ---- map: out_f32 = A @ W + bias. AH=1: A is half ----
template <int AH>
__global__ void __launch_bounds__(512, 1) map_kernel(
    const void* __restrict__ A, const uint32_t* __restrict__ Wp,
    const float* __restrict__ bias, float* __restrict__ out, int n)
{
    extern __shared__ char raw[];
    SmemM* s = (SmemM*)raw;
    const int tid = threadIdx.x, lane = tid & 31, warp = tid >> 5;
    const int wm = warp >> 2, wn = warp & 3, g = lane >> 2, tig = lane & 3;
    const int row0 = blockIdx.x * 128;

    fetch_tile(smem_u32(s->w), Wp, tid);
    if (AH) fill_act_h(smem_u32(s->act), (const uint32_t*)A, row0, n, tid);
    CP_COMMIT();
    if (!AH) fill_act_f(s->act, (const float*)A, row0, n, tid);
    CP_WAIT0();
    __syncthreads();

    float acc[2][4][4];
    gemm_h(s->act, s->w, acc, wm, wn, g, tig);

    float2 bv[4];
#pragma unroll
    for (int j = 0; j < 4; j++) bv[j] = *(const float2*)(bias + wn * 32 + j * 8 + 2 * tig);
#pragma unroll
    for (int mt = 0; mt < 2; mt++) {
        int gr0 = row0 + wm * 32 + mt * 16 + g, gr1 = gr0 + 8;
#pragma unroll
        for (int j = 0; j < 4; j++) {
            int cc = wn * 32 + j * 8 + 2 * tig;
            if (gr0 < n)
                *(float2*)(out + (size_t)gr0 * 128 + cc) =
                    make_float2(acc[mt][j][0] + bv[j].x, acc[mt][j][1] + bv[j].y);
            if (gr1 < n)
                *(float2*)(out + (size_t)gr1 * 128 + cc) =
                    make_float2(acc[mt][j][2] + bv[j].x, acc[mt][j][3] + bv[j].y);
        }
    }
}

// ---- fused quad. A1H/A2H: source dtype flags ----
template <int A1H, int A2H>
__global__ void __launch_bounds__(512, 1) quad_kernel(
    const void* __restrict__ A1, const void* __restrict__ A2,
    const uint32_t* __restrict__ W1a, const float* __restrict__ b1a,
    const float* __restrict__ g1a, const float* __restrict__ n1a,
    const uint32_t* __restrict__ W2a, const float* __restrict__ b2a,
    const uint32_t* __restrict__ W1b, const float* __restrict__ b1b,
    const float* __restrict__ g1b, const float* __restrict__ n1b,
    const uint32_t* __restrict__ W2b, const float* __restrict__ b2b,
    const int* __restrict__ batch, float* __restrict__ out, int n)
{
    extern __shared__ char raw[];
    SmemH* s = (SmemH*)raw;
    const int tid = threadIdx.x, lane = tid & 31, warp = tid >> 5;
    const int wm = warp >> 2, wn = warp & 3, g = lane >> 2, tig = lane & 3;
    const int row0 = blockIdx.x * 128;

    fetch_tile(smem_u32(s->w[0]), W1a, tid);
    fetch_tile(smem_u32(s->w[1]), W2a, tid);
    fetch_tile(smem_u32(s->w[2]), W1b, tid);
    fetch_tile(smem_u32(s->w[3]), W2b, tid);
    if (A1H) fill_act_h(smem_u32(s->act), (const uint32_t*)A1, row0, n, tid);
    CP_COMMIT();
    if (tid < 128) s->sbatch[tid] = (row0 + tid < n) ? batch[row0 + tid] : -1;
    if (!A1H) fill_act_f(s->act, (const float*)A1, row0, n, tid);
    CP_WAIT0();
    __syncthreads();

    float acc[2][4][4];
    gemm_h(s->act, s->w[0], acc, wm, wn, g, tig);
    ln_mish_act(s, acc, b1a, g1a, n1a, wm, wn, g, tig);
    gemm_h(s->act, s->w[1], acc, wm, wn, g, tig);

    float vv[2][4][4];
    {
        float2 b2[4];
#pragma unroll
        for (int j = 0; j < 4; j++) b2[j] = *(const float2*)(b2a + wn * 32 + j * 8 + 2 * tig);
#pragma unroll
        for (int mt = 0; mt < 2; mt++)
#pragma unroll
            for (int j = 0; j < 4; j++) {
                vv[mt][j][0] = acc[mt][j][0] + b2[j].x;
                vv[mt][j][1] = acc[mt][j][1] + b2[j].y;
                vv[mt][j][2] = acc[mt][j][2] + b2[j].x;
                vv[mt][j][3] = acc[mt][j][3] + b2[j].y;
            }
    }
    __syncthreads();                 // all warps done reading act (h1v)

    // key side
    if (A2H) {
        fill_act_h(smem_u32(s->act), (const uint32_t*)A2, row0, n, tid);
        CP_COMMIT();
        CP_WAIT0();
    } else {
        fill_act_f(s->act, (const float*)A2, row0, n, tid);
    }
    __syncthreads();
    gemm_h(s->act, s->w[2], acc, wm, wn, g, tig);
    ln_mish_act(s, acc, b1b, g1b, n1b, wm, wn, g, tig);
    gemm_h(s->act, s->w[3], acc, wm, wn, g, tig);
    __syncthreads();

    float* Y = (float*)s->w[0];
    {
        float2 b2[4];
#pragma unroll
        for (int j = 0; j < 4; j++) b2[j] = *(const float2*)(b2b + wn * 32 + j * 8 + 2 * tig);
#pragma unroll
        for (int mt = 0; mt < 2; mt++) {
            int r0 = wm * 32 + mt * 16 + g, r1 = r0 + 8;
#pragma unroll
            for (int j = 0; j < 4; j++) {
                int cc = wn * 32 + j * 8 + 2 * tig;
                *(float2*)&Y[r0 * 132 + cc] = make_float2(
                    (acc[mt][j][0] + b2[j].x) * vv[mt][j][0],
                    (acc[mt][j][1] + b2[j].y) * vv[mt][j][1]);
                *(float2*)&Y[r1 * 132 + cc] = make_float2(
                    (acc[mt][j][2] + b2[j].x) * vv[mt][j][2],
                    (acc[mt][j][3] + b2[j].y) * vv[mt][j][3]);
            }
        }
    }
    __syncthreads();

    {
        int c = tid & 127, qq = tid >> 7;
        int r = qq * 32;
        float a = 0.f;
        int cur = s->sbatch[r];
#pragma unroll 4
        for (int i = 0; i < 32; i++, r++) {
            int sbv = s->sbatch[r];
            if (sbv != cur) {
                if (cur >= 0) atomicAdd(out + (size_t)cur * 128 + c, a);
                a = 0.f; cur = sbv;
            }
            a += Y[r * 132 + c];
        }
        if (cur >= 0) atomicAdd(out + (size_t)cur * 128 + c, a);
    }
}

extern "C" void kernel_launch(void* const* d_in, const int* in_sizes, int n_in,
                              void* d_out, int out_size)
{
    const float* x     = (const float*)d_in[0];
    const int*   batch = (const int*)  d_in[1];
    const float* W_map = (const float*)d_in[3];
    const float* b_map = (const float*)d_in[4];
    const float* kW1 = (const float*)d_in[5],  *kb1 = (const float*)d_in[6];
    const float* kg  = (const float*)d_in[7],  *kbn = (const float*)d_in[8];
    const float* kW2 = (const float*)d_in[9],  *kb2 = (const float*)d_in[10];
    const float* vW1 = (const float*)d_in[11], *vb1 = (const float*)d_in[12];
    const float* vg  = (const float*)d_in[13], *vbn = (const float*)d_in[14];
    const float* vW2 = (const float*)d_in[15], *vb2 = (const float*)d_in[16];
    const float* iW_map = (const float*)d_in[17], *ib_map = (const float*)d_in[18];
    const float* ikW1 = (const float*)d_in[19], *ikb1 = (const float*)d_in[20];
    const float* ikg  = (const float*)d_in[21], *ikbn = (const float*)d_in[22];
    const float* ikW2 = (const float*)d_in[23], *ikb2 = (const float*)d_in[24];
    const float* ivW1 = (const float*)d_in[25], *ivb1 = (const float*)d_in[26];
    const float* ivg  = (const float*)d_in[27], *ivbn = (const float*)d_in[28];
    const float* ivW2 = (const float*)d_in[29], *ivb2 = (const float*)d_in[30];

    int n = in_sizes[0] / 128;
    float* out = (float*)d_out;

    float *key0, *key0b; uint32_t *keysh, *k2h, *wprep; int* segstart;
    cudaGetSymbolAddress((void**)&key0,  g_key0);
    cudaGetSymbolAddress((void**)&key0b, g_key0b);
    cudaGetSymbolAddress((void**)&keysh, g_keysh);
    cudaGetSymbolAddress((void**)&k2h,   g_k2h);
    cudaGetSymbolAddress((void**)&segstart, g_segstart);
    cudaGetSymbolAddress((void**)&wprep, g_wprep);

    cudaFuncSetAttribute(map_kernel<0>, cudaFuncAttributeMaxDynamicSharedMemorySize, (int)sizeof(SmemM));
    cudaFuncSetAttribute(map_kernel<1>, cudaFuncAttributeMaxDynamicSharedMemorySize, (int)sizeof(SmemM));
    cudaFuncSetAttribute(quad_kernel<0,1>, cudaFuncAttributeMaxDynamicSharedMemorySize, (int)sizeof(SmemH));
    cudaFuncSetAttribute(quad_kernel<1,1>, cudaFuncAttributeMaxDynamicSharedMemorySize, (int)sizeof(SmemH));

    cudaMemsetAsync(d_out, 0, (size_t)out_size * sizeof(float));
    segstart_kernel<<<(NBATCH + 256) / 256, 256>>>(batch, n, segstart);
    // slots: 0=W_map 1=kW1 2=kW2 3=vW1 4=vW2 5=iW_map 6=ikW1 7=ikW2 8=ivW1 9=ivW2
    prep_all<<<dim3(32, 10), 256>>>(W_map, kW1, kW2, vW1, vW2, iW_map, ikW1, ikW2, ivW1, ivW2);

    int mb = (n + 127) / 128;
#define WSLOT(i) (wprep + (size_t)(i) * TILE_W)

    // outer encoder
    map_kernel<0><<<mb, 512, sizeof(SmemM)>>>(x, WSLOT(0), b_map, key0, n);
    seg_softmax_h<<<NBATCH, 128>>>(key0, (__half*)keysh, segstart);
    quad_kernel<0,1><<<mb, 512, sizeof(SmemH)>>>(x, keysh,
                                  WSLOT(3), vb1, vg, vbn, WSLOT(4), vb2,
                                  WSLOT(1), kb1, kg, kbn, WSLOT(2), kb2,
                                  batch, out, n);

    // inner encoder
    map_kernel<1><<<mb, 512, sizeof(SmemM)>>>(keysh, WSLOT(5), ib_map, key0b, n);
    seg_softmax_h<<<NBATCH, 128>>>(key0b, (__half*)k2h, segstart);
    quad_kernel<1,1><<<mb, 512, sizeof(SmemH)>>>(keysh, k2h,
                                  WSLOT(8), ivb1, ivg, ivbn, WSLOT(9), ivb2,
                                  WSLOT(6), ikb1, ikg, ikbn, WSLOT(7), ikb2,
                                  batch, out + (size_t)NBATCH * 128, n);
}

// round 17
// speedup vs baseline: 2.1277x; 1.0191x over previous
#include <cuda_runtime.h>
#include <cuda_fp16.h>
#include <math.h>
#include <stdint.h>

#define MAXN   500000
#define NBATCH 4096
#define AW     68                 // smem row stride in 32-bit words (128 halves + pad)
#define TILE_W (128 * AW)
#define TILE_C (TILE_W / 4)

// ---- static scratch ----
__device__ __align__(16) float    g_key0 [(size_t)MAXN * 128];   // pre-softmax (fp32)
__device__ __align__(16) float    g_key0b[(size_t)MAXN * 128];   // inner pre-softmax (fp32)
__device__ __align__(16) uint32_t g_keysh[(size_t)MAXN * 64];    // softmaxed keys (half2)
__device__ __align__(16) uint32_t g_k2h  [(size_t)MAXN * 64];    // softmaxed inner keys (half2)
__device__ __align__(16) uint32_t g_wprep[10 * TILE_W];          // half2 [n][k], stride AW
__device__ int g_segstart[NBATCH + 1];

struct SmemH {                     // quad: ~213.5 KB
    uint32_t act [TILE_W];         // A1 / h1v
    uint32_t act2[TILE_W];         // A2 (prefetched) / h1k
    uint32_t w[4][TILE_W];         // w[0..1] reused as Y (float, stride 132)
    float    ssum[128][4];
    float    ssq [128][4];
    int      sbatch[128];
};
struct SmemM {                     // map
    uint32_t act[TILE_W];
    uint32_t w[TILE_W];
};

__device__ __forceinline__ float mish_f(float x) {
    float sp = (x > 20.f) ? x : log1pf(__expf(x));
    return x * tanhf(sp);
}
__device__ __forceinline__ uint32_t pack_h2(float lo, float hi) {
    uint32_t r;
    asm("cvt.rn.f16x2.f32 %0, %1, %2;" : "=r"(r) : "f"(hi), "f"(lo));
    return r;
}
__device__ __forceinline__ uint32_t smem_u32(const void* p) {
    uint32_t a;
    asm("{ .reg .u64 t; cvta.to.shared.u64 t, %1; cvt.u32.u64 %0, t; }" : "=r"(a) : "l"(p));
    return a;
}
__device__ __forceinline__ void mma16(float c[4], uint32_t a0, uint32_t a1, uint32_t a2,
                                      uint32_t a3, uint32_t b0, uint32_t b1) {
    asm volatile("mma.sync.aligned.m16n8k16.row.col.f32.f16.f16.f32 "
        "{%0,%1,%2,%3},{%4,%5,%6,%7},{%8,%9},{%0,%1,%2,%3};"
        : "+f"(c[0]), "+f"(c[1]), "+f"(c[2]), "+f"(c[3])
        : "r"(a0), "r"(a1), "r"(a2), "r"(a3), "r"(b0), "r"(b1));
}
__device__ __forceinline__ void ldsm_x4(uint32_t r[4], uint32_t addr) {
    asm volatile("ldmatrix.sync.aligned.m8n8.x4.shared.b16 {%0,%1,%2,%3}, [%4];"
        : "=r"(r[0]), "=r"(r[1]), "=r"(r[2]), "=r"(r[3]) : "r"(addr));
}

// ---- segment starts ----
__global__ void segstart_kernel(const int* __restrict__ batch, int n, int* __restrict__ segstart) {
    int b = blockIdx.x * blockDim.x + threadIdx.x;
    if (b > NBATCH) return;
    int lo = 0, hi = n;
    while (lo < hi) { int m = (lo + hi) >> 1; if (batch[m] < b) lo = m + 1; else hi = m; }
    segstart[b] = lo;
}

// ---- weight prep: W[k][n] fp32 -> half2 [n][k], stride AW ----
__global__ void prep_all(const float* w0, const float* w1, const float* w2, const float* w3,
                         const float* w4, const float* w5, const float* w6, const float* w7,
                         const float* w8, const float* w9) {
    const float* srcs[10] = {w0, w1, w2, w3, w4, w5, w6, w7, w8, w9};
    int wi = blockIdx.y;
    const float* W = srcs[wi];
    int e = blockIdx.x * 256 + threadIdx.x;       // 0..8191
    int nn = e >> 6, wk = e & 63;
    int k = wk * 2;
    g_wprep[wi * TILE_W + nn * AW + wk] = pack_h2(W[k * 128 + nn], W[(k + 1) * 128 + nn]);
}

// ---- softmax: fp32 in, fp16 out ----
__global__ void __launch_bounds__(128) seg_softmax_h(
    const float* __restrict__ in, __half* __restrict__ outh,
    const int* __restrict__ segstart)
{
    int b = blockIdx.x;
    int s0 = segstart[b], e = segstart[b + 1];
    int t = threadIdx.x;
    if (s0 >= e) return;
    float m0 = -3.4e38f, m1 = -3.4e38f, m2 = -3.4e38f, m3 = -3.4e38f;
    float d0 = 0.f, d1 = 0.f, d2 = 0.f, d3 = 0.f;
    int r = s0;
    for (; r + 3 < e; r += 4) {
        float v0 = in[(size_t)(r + 0) * 128 + t];
        float v1 = in[(size_t)(r + 1) * 128 + t];
        float v2 = in[(size_t)(r + 2) * 128 + t];
        float v3 = in[(size_t)(r + 3) * 128 + t];
        float n0 = fmaxf(m0, v0); d0 = d0 * __expf(m0 - n0) + __expf(v0 - n0); m0 = n0;
        float n1 = fmaxf(m1, v1); d1 = d1 * __expf(m1 - n1) + __expf(v1 - n1); m1 = n1;
        float n2 = fmaxf(m2, v2); d2 = d2 * __expf(m2 - n2) + __expf(v2 - n2); m2 = n2;
        float n3 = fmaxf(m3, v3); d3 = d3 * __expf(m3 - n3) + __expf(v3 - n3); m3 = n3;
    }
    for (; r < e; r++) {
        float v = in[(size_t)r * 128 + t];
        float nm = fmaxf(m0, v); d0 = d0 * __expf(m0 - nm) + __expf(v - nm); m0 = nm;
    }
    float m = fmaxf(fmaxf(m0, m1), fmaxf(m2, m3));
    float d = d0 * __expf(m0 - m) + d1 * __expf(m1 - m)
            + d2 * __expf(m2 - m) + d3 * __expf(m3 - m);
    float inv = 1.f / d;
    for (r = s0; r < e; r++) {
        float v = in[(size_t)r * 128 + t];
        outh[(size_t)r * 128 + t] = __float2half_rn(__expf(v - m) * inv);
    }
}

// ---- cp.async prefetch of one prepped weight tile ----
__device__ __forceinline__ void fetch_tile(uint32_t dst, const uint32_t* __restrict__ src, int tid) {
#pragma unroll
    for (int i = 0; i < 5; i++) {
        int idx = tid + i * 512;
        if (idx < TILE_C)
            asm volatile("cp.async.cg.shared.global [%0], [%1], 16;"
                         :: "r"(dst + idx * 16), "l"(src + idx * 4) : "memory");
    }
}
#define CP_COMMIT() asm volatile("cp.async.commit_group;" ::: "memory")
#define CP_WAIT(N)  asm volatile("cp.async.wait_group %0;" :: "n"(N) : "memory")

// ---- fill act from fp32 source (convert) ----
__device__ __forceinline__ void fill_act_f(uint32_t* __restrict__ act, const float* __restrict__ src,
                                           int row0, int n, int tid) {
#pragma unroll
    for (int i = 0; i < 8; i++) {
        int e = tid + i * 512;
        int r = e >> 5, c4 = (e & 31) * 4;
        int gr = row0 + r;
        float4 v = make_float4(0.f, 0.f, 0.f, 0.f);
        if (gr < n) v = *(const float4*)(src + (size_t)gr * 128 + c4);
        uint2 st;
        st.x = pack_h2(v.x, v.y);
        st.y = pack_h2(v.z, v.w);
        *(uint2*)&act[r * AW + (e & 31) * 2] = st;
    }
}

// ---- fill act from half source via cp.async (zero-fill past n) ----
__device__ __forceinline__ void fill_act_h(uint32_t act_addr, const uint32_t* __restrict__ srch,
                                           int row0, int n, int tid) {
#pragma unroll
    for (int i = 0; i < 4; i++) {
        int e = tid + i * 512;                    // 0..2047 = 128 rows x 16 chunks
        int r = e >> 4, c = e & 15;
        int gr = row0 + r;
        int sz = (gr < n) ? 16 : 0;
        size_t so = (size_t)(gr < n ? gr : 0) * 64 + c * 4;
        asm volatile("cp.async.cg.shared.global [%0], [%1], 16, %2;"
                     :: "r"(act_addr + (uint32_t)((r * AW + c * 4) * 4)),
                        "l"(srch + so), "r"(sz) : "memory");
    }
}

// ---- GEMM core with ldmatrix: acc[128x128] = act @ W ----
// 16 warps, warp tile 32x32. LDSM lane row: ((lane>>3)&1)*8 + (lane&7); k-word: (lane>>4)*4.
__device__ __forceinline__ void gemm_h(const uint32_t* __restrict__ act,
                                       const uint32_t* __restrict__ w,
                                       float acc[2][4][4],
                                       int wm, int wn, int lane) {
    const int lrow  = ((lane >> 3) & 1) * 8 + (lane & 7);
    const int lwoff = (lane >> 4) * 4;
    uint32_t abase = smem_u32(act) + (uint32_t)(((wm * 32 + lrow) * AW + lwoff) * 4);
    uint32_t bbase = smem_u32(w)   + (uint32_t)(((wn * 32 + lrow) * AW + lwoff) * 4);
#pragma unroll
    for (int mt = 0; mt < 2; mt++)
#pragma unroll
        for (int j = 0; j < 4; j++)
#pragma unroll
            for (int c = 0; c < 4; c++) acc[mt][j][c] = 0.f;

#pragma unroll
    for (int ks = 0; ks < 8; ks++) {
        const uint32_t ko = ks * 32;              // 8 words = 32 bytes per k-step
        uint32_t a0[4], a1[4], b0[4], b1[4];
        ldsm_x4(a0, abase + ko);                          // A rows wm*32..+16
        ldsm_x4(a1, abase + 16 * AW * 4 + ko);            // A rows +16..+32
        ldsm_x4(b0, bbase + ko);                          // B cols wn*32..+16
        ldsm_x4(b1, bbase + 16 * AW * 4 + ko);            // B cols +16..+32
        mma16(acc[0][0], a0[0], a0[1], a0[2], a0[3], b0[0], b0[2]);
        mma16(acc[0][1], a0[0], a0[1], a0[2], a0[3], b0[1], b0[3]);
        mma16(acc[0][2], a0[0], a0[1], a0[2], a0[3], b1[0], b1[2]);
        mma16(acc[0][3], a0[0], a0[1], a0[2], a0[3], b1[1], b1[3]);
        mma16(acc[1][0], a1[0], a1[1], a1[2], a1[3], b0[0], b0[2]);
        mma16(acc[1][1], a1[0], a1[1], a1[2], a1[3], b0[1], b0[3]);
        mma16(acc[1][2], a1[0], a1[1], a1[2], a1[3], b1[0], b1[2]);
        mma16(acc[1][3], a1[0], a1[1], a1[2], a1[3], b1[1], b1[3]);
    }
}

// ---- bias + layernorm + mish; write result (half2) into dst_act ----
__device__ __forceinline__ void ln_mish_act(SmemH* s, uint32_t* __restrict__ dst_act,
    float acc[2][4][4],
    const float* __restrict__ bias, const float* __restrict__ gam, const float* __restrict__ bet,
    int wm, int wn, int g, int tig)
{
    float2 bv[4], gv[4], bb[4];
#pragma unroll
    for (int j = 0; j < 4; j++) {
        int cc = wn * 32 + j * 8 + 2 * tig;
        bv[j] = *(const float2*)(bias + cc);
        gv[j] = *(const float2*)(gam + cc);
        bb[j] = *(const float2*)(bet + cc);
    }
#pragma unroll
    for (int mt = 0; mt < 2; mt++) {
        float s0 = 0.f, q0 = 0.f, s1 = 0.f, q1 = 0.f;
#pragma unroll
        for (int j = 0; j < 4; j++) {
            float a0 = acc[mt][j][0] + bv[j].x, a1 = acc[mt][j][1] + bv[j].y;
            float a2 = acc[mt][j][2] + bv[j].x, a3 = acc[mt][j][3] + bv[j].y;
            acc[mt][j][0] = a0; acc[mt][j][1] = a1; acc[mt][j][2] = a2; acc[mt][j][3] = a3;
            s0 += a0 + a1; q0 += a0 * a0 + a1 * a1;
            s1 += a2 + a3; q1 += a2 * a2 + a3 * a3;
        }
#pragma unroll
        for (int o = 1; o <= 2; o <<= 1) {
            s0 += __shfl_xor_sync(0xffffffffu, s0, o);
            q0 += __shfl_xor_sync(0xffffffffu, q0, o);
            s1 += __shfl_xor_sync(0xffffffffu, s1, o);
            q1 += __shfl_xor_sync(0xffffffffu, q1, o);
        }
        if (tig == 0) {
            int r = wm * 32 + mt * 16 + g;
            s->ssum[r][wn] = s0; s->ssq[r][wn] = q0;
            s->ssum[r + 8][wn] = s1; s->ssq[r + 8][wn] = q1;
        }
    }
    __syncthreads();   // partials ready; all warps done reading source act
#pragma unroll
    for (int mt = 0; mt < 2; mt++) {
        int r0 = wm * 32 + mt * 16 + g, r1 = r0 + 8;
        float su0 = s->ssum[r0][0] + s->ssum[r0][1] + s->ssum[r0][2] + s->ssum[r0][3];
        float sq0 = s->ssq [r0][0] + s->ssq [r0][1] + s->ssq [r0][2] + s->ssq [r0][3];
        float mean0 = su0 * (1.f / 128.f);
        float var0  = sq0 * (1.f / 128.f) - mean0 * mean0;
        float rs0   = rsqrtf(var0 + 1e-5f);
        float su1 = s->ssum[r1][0] + s->ssum[r1][1] + s->ssum[r1][2] + s->ssum[r1][3];
        float sq1 = s->ssq [r1][0] + s->ssq [r1][1] + s->ssq [r1][2] + s->ssq [r1][3];
        float mean1 = su1 * (1.f / 128.f);
        float var1  = sq1 * (1.f / 128.f) - mean1 * mean1;
        float rs1   = rsqrtf(var1 + 1e-5f);
#pragma unroll
        for (int j = 0; j < 4; j++) {
            int wd = wn * 16 + j * 4 + tig;
            float o0 = mish_f((acc[mt][j][0] - mean0) * rs0 * gv[j].x + bb[j].x);
            float o1 = mish_f((acc[mt][j][1] - mean0) * rs0 * gv[j].y + bb[j].y);
            float o2 = mish_f((acc[mt][j][2] - mean1) * rs1 * gv[j].x + bb[j].x);
            float o3 = mish_f((acc[mt][j][3] - mean1) * rs1 * gv[j].y + bb[j].y);
            dst_act[r0 * AW + wd] = pack_h2(o0, o1);
            dst_act[r1 * AW + wd] = pack_h2(o2, o3);
        }
    }
    __syncthreads();
}

// ---- map: out_f32 = A @ W + bias. AH=1: A is half ----
template <int AH>
__global__ void __launch_bounds__(512, 1) map_kernel(
    const void* __restrict__ A, const uint32_t* __restrict__ Wp,
    const float* __restrict__ bias, float* __restrict__ out, int n)
{
    extern __shared__ char raw[];
    SmemM* s = (SmemM*)raw;
    const int tid = threadIdx.x, lane = tid & 31, warp = tid >> 5;
    const int wm = warp >> 2, wn = warp & 3, g = lane >> 2, tig = lane & 3;
    const int row0 = blockIdx.x * 128;

    fetch_tile(smem_u32(s->w), Wp, tid);
    if (AH) fill_act_h(smem_u32(s->act), (const uint32_t*)A, row0, n, tid);
    CP_COMMIT();
    if (!AH) fill_act_f(s->act, (const float*)A, row0, n, tid);
    CP_WAIT(0);
    __syncthreads();

    float acc[2][4][4];
    gemm_h(s->act, s->w, acc, wm, wn, lane);

    float2 bv[4];
#pragma unroll
    for (int j = 0; j < 4; j++) bv[j] = *(const float2*)(bias + wn * 32 + j * 8 + 2 * tig);
#pragma unroll
    for (int mt = 0; mt < 2; mt++) {
        int gr0 = row0 + wm * 32 + mt * 16 + g, gr1 = gr0 + 8;
#pragma unroll
        for (int j = 0; j < 4; j++) {
            int cc = wn * 32 + j * 8 + 2 * tig;
            if (gr0 < n)
                *(float2*)(out + (size_t)gr0 * 128 + cc) =
                    make_float2(acc[mt][j][0] + bv[j].x, acc[mt][j][1] + bv[j].y);
            if (gr1 < n)
                *(float2*)(out + (size_t)gr1 * 128 + cc) =
                    make_float2(acc[mt][j][2] + bv[j].x, acc[mt][j][3] + bv[j].y);
        }
    }
}

// ---- fused quad. A1H: A1 dtype flag; A2 is always half (prefetched into act2) ----
template <int A1H>
__global__ void __launch_bounds__(512, 1) quad_kernel(
    const void* __restrict__ A1, const uint32_t* __restrict__ A2h,
    const uint32_t* __restrict__ W1a, const float* __restrict__ b1a,
    const float* __restrict__ g1a, const float* __restrict__ n1a,
    const uint32_t* __restrict__ W2a, const float* __restrict__ b2a,
    const uint32_t* __restrict__ W1b, const float* __restrict__ b1b,
    const float* __restrict__ g1b, const float* __restrict__ n1b,
    const uint32_t* __restrict__ W2b, const float* __restrict__ b2b,
    const int* __restrict__ batch, float* __restrict__ out, int n)
{
    extern __shared__ char raw[];
    SmemH* s = (SmemH*)raw;
    const int tid = threadIdx.x, lane = tid & 31, warp = tid >> 5;
    const int wm = warp >> 2, wn = warp & 3, g = lane >> 2, tig = lane & 3;
    const int row0 = blockIdx.x * 128;

    // group 0: weights (+A1 if half). group 1: A2 prefetch (consumed much later).
    fetch_tile(smem_u32(s->w[0]), W1a, tid);
    fetch_tile(smem_u32(s->w[1]), W2a, tid);
    fetch_tile(smem_u32(s->w[2]), W1b, tid);
    fetch_tile(smem_u32(s->w[3]), W2b, tid);
    if (A1H) fill_act_h(smem_u32(s->act), (const uint32_t*)A1, row0, n, tid);
    CP_COMMIT();
    fill_act_h(smem_u32(s->act2), A2h, row0, n, tid);
    CP_COMMIT();
    if (tid < 128) s->sbatch[tid] = (row0 + tid < n) ? batch[row0 + tid] : -1;
    if (!A1H) fill_act_f(s->act, (const float*)A1, row0, n, tid);
    CP_WAIT(1);                       // group 0 (weights + A1) complete
    __syncthreads();

    float acc[2][4][4];
    // val side: h1v = LN/mish(A1@W1a + b1a) -> act; v = h1v@W2a + b2a (regs)
    gemm_h(s->act, s->w[0], acc, wm, wn, lane);
    ln_mish_act(s, s->act, acc, b1a, g1a, n1a, wm, wn, g, tig);
    gemm_h(s->act, s->w[1], acc, wm, wn, lane);

    float vv[2][4][4];
    {
        float2 b2[4];
#pragma unroll
        for (int j = 0; j < 4; j++) b2[j] = *(const float2*)(b2a + wn * 32 + j * 8 + 2 * tig);
#pragma unroll
        for (int mt = 0; mt < 2; mt++)
#pragma unroll
            for (int j = 0; j < 4; j++) {
                vv[mt][j][0] = acc[mt][j][0] + b2[j].x;
                vv[mt][j][1] = acc[mt][j][1] + b2[j].y;
                vv[mt][j][2] = acc[mt][j][2] + b2[j].x;
                vv[mt][j][3] = acc[mt][j][3] + b2[j].y;
            }
    }
    CP_WAIT(0);                       // A2 long since landed in act2
    __syncthreads();

    // key side: kq = mlp2(A2); y = kq * v
    gemm_h(s->act2, s->w[2], acc, wm, wn, lane);
    ln_mish_act(s, s->act2, acc, b1b, g1b, n1b, wm, wn, g, tig);
    gemm_h(s->act2, s->w[3], acc, wm, wn, lane);
    __syncthreads();                  // all warps done reading act2 and w[0..1]

    float* Y = (float*)s->w[0];
    {
        float2 b2[4];
#pragma unroll
        for (int j = 0; j < 4; j++) b2[j] = *(const float2*)(b2b + wn * 32 + j * 8 + 2 * tig);
#pragma unroll
        for (int mt = 0; mt < 2; mt++) {
            int r0 = wm * 32 + mt * 16 + g, r1 = r0 + 8;
#pragma unroll
            for (int j = 0; j < 4; j++) {
                int cc = wn * 32 + j * 8 + 2 * tig;
                *(float2*)&Y[r0 * 132 + cc] = make_float2(
                    (acc[mt][j][0] + b2[j].x) * vv[mt][j][0],
                    (acc[mt][j][1] + b2[j].y) * vv[mt][j][1]);
                *(float2*)&Y[r1 * 132 + cc] = make_float2(
                    (acc[mt][j][2] + b2[j].x) * vv[mt][j][2],
                    (acc[mt][j][3] + b2[j].y) * vv[mt][j][3]);
            }
        }
    }
    __syncthreads();

    {
        int c = tid & 127, qq = tid >> 7;
        int r = qq * 32;
        float a = 0.f;
        int cur = s->sbatch[r];
#pragma unroll 4
        for (int i = 0; i < 32; i++, r++) {
            int sbv = s->sbatch[r];
            if (sbv != cur) {
                if (cur >= 0) atomicAdd(out + (size_t)cur * 128 + c, a);
                a = 0.f; cur = sbv;
            }
            a += Y[r * 132 + c];
        }
        if (cur >= 0) atomicAdd(out + (size_t)cur * 128 + c, a);
    }
}

extern "C" void kernel_launch(void* const* d_in, const int* in_sizes, int n_in,
                              void* d_out, int out_size)
{
    const float* x     = (const float*)d_in[0];
    const int*   batch = (const int*)  d_in[1];
    const float* W_map = (const float*)d_in[3];
    const float* b_map = (const float*)d_in[4];
    const float* kW1 = (const float*)d_in[5],  *kb1 = (const float*)d_in[6];
    const float* kg  = (const float*)d_in[7],  *kbn = (const float*)d_in[8];
    const float* kW2 = (const float*)d_in[9],  *kb2 = (const float*)d_in[10];
    const float* vW1 = (const float*)d_in[11], *vb1 = (const float*)d_in[12];
    const float* vg  = (const float*)d_in[13], *vbn = (const float*)d_in[14];
    const float* vW2 = (const float*)d_in[15], *vb2 = (const float*)d_in[16];
    const float* iW_map = (const float*)d_in[17], *ib_map = (const float*)d_in[18];
    const float* ikW1 = (const float*)d_in[19], *ikb1 = (const float*)d_in[20];
    const float* ikg  = (const float*)d_in[21], *ikbn = (const float*)d_in[22];
    const float* ikW2 = (const float*)d_in[23], *ikb2 = (const float*)d_in[24];
    const float* ivW1 = (const float*)d_in[25], *ivb1 = (const float*)d_in[26];
    const float* ivg  = (const float*)d_in[27], *ivbn = (const float*)d_in[28];
    const float* ivW2 = (const float*)d_in[29], *ivb2 = (const float*)d_in[30];

    int n = in_sizes[0] / 128;
    float* out = (float*)d_out;

    float *key0, *key0b; uint32_t *keysh, *k2h, *wprep; int* segstart;
    cudaGetSymbolAddress((void**)&key0,  g_key0);
    cudaGetSymbolAddress((void**)&key0b, g_key0b);
    cudaGetSymbolAddress((void**)&keysh, g_keysh);
    cudaGetSymbolAddress((void**)&k2h,   g_k2h);
    cudaGetSymbolAddress((void**)&segstart, g_segstart);
    cudaGetSymbolAddress((void**)&wprep, g_wprep);

    cudaFuncSetAttribute(map_kernel<0>, cudaFuncAttributeMaxDynamicSharedMemorySize, (int)sizeof(SmemM));
    cudaFuncSetAttribute(map_kernel<1>, cudaFuncAttributeMaxDynamicSharedMemorySize, (int)sizeof(SmemM));
    cudaFuncSetAttribute(quad_kernel<0>, cudaFuncAttributeMaxDynamicSharedMemorySize, (int)sizeof(SmemH));
    cudaFuncSetAttribute(quad_kernel<1>, cudaFuncAttributeMaxDynamicSharedMemorySize, (int)sizeof(SmemH));

    cudaMemsetAsync(d_out, 0, (size_t)out_size * sizeof(float));
    segstart_kernel<<<(NBATCH + 256) / 256, 256>>>(batch, n, segstart);
    // slots: 0=W_map 1=kW1 2=kW2 3=vW1 4=vW2 5=iW_map 6=ikW1 7=ikW2 8=ivW1 9=ivW2
    prep_all<<<dim3(32, 10), 256>>>(W_map, kW1, kW2, vW1, vW2, iW_map, ikW1, ikW2, ivW1, ivW2);

    int mb = (n + 127) / 128;
#define WSLOT(i) (wprep + (size_t)(i) * TILE_W)

    // outer encoder
    map_kernel<0><<<mb, 512, sizeof(SmemM)>>>(x, WSLOT(0), b_map, key0, n);
    seg_softmax_h<<<NBATCH, 128>>>(key0, (__half*)keysh, segstart);
    quad_kernel<0><<<mb, 512, sizeof(SmemH)>>>(x, keysh,
                                  WSLOT(3), vb1, vg, vbn, WSLOT(4), vb2,
                                  WSLOT(1), kb1, kg, kbn, WSLOT(2), kb2,
                                  batch, out, n);

    // inner encoder
    map_kernel<1><<<mb, 512, sizeof(SmemM)>>>(keysh, WSLOT(5), ib_map, key0b, n);
    seg_softmax_h<<<NBATCH, 128>>>(key0b, (__half*)k2h, segstart);
    quad_kernel<1><<<mb, 512, sizeof(SmemH)>>>(keysh, k2h,
                                  WSLOT(8), ivb1, ivg, ivbn, WSLOT(9), ivb2,
                                  WSLOT(6), ikb1, ikg, ikbn, WSLOT(7), ikb2,
                                  batch, out + (size_t)NBATCH * 128, n);
}